// round 4
// baseline (speedup 1.0000x reference)
#include <cuda_runtime.h>
#include <math.h>

// Binarized AlexNet_OWT pipeline, all-integer / XNOR-popcount formulation.
//
// Shapes:
//  x   [4096,12,12,15]
//  L1: conv(pad1) -> [B,48,12,15], pool k2s1 -> [B,48,11,14] (154), BN thresh
//  L2: conv(pad0) -> [B,48,9,12] (108), BN thresh
//  L3: conv(pad0) -> [B,48,7,10], pool -> [B,48,6,9] (54), BN thresh
//  FC: [B,2592] x sign(wfc[5,2592])^T -> [B,5]
//
// Output d_out = concat(out, xb1, xb2, xb3, fb) flattened, all float32.

#define BATCH 4096

#define OUT_OFF 0u
#define XB1_OFF 20480u
#define XB2_OFF 8867840u
#define XB3_OFF 39145472u
#define FB_OFF  60379136u

// ---------------- scratch (static __device__; no allocations) ----------------
__device__ unsigned short      g_xp1[BATCH * 180];        // packed input bits (12 ch)
__device__ unsigned short      g_wp1[48 * 9];
__device__ unsigned long long  g_wp2[48 * 9];
__device__ unsigned long long  g_wp3[48 * 9];
__device__ unsigned int        g_wfcp[5 * 81];
__device__ signed char         g_pool1[BATCH * 48 * 154]; // |v| <= 108
__device__ unsigned long long  g_xp2[BATCH * 154];
__device__ short               g_conv2[BATCH * 48 * 108]; // |v| <= 432
__device__ unsigned long long  g_xp3[BATCH * 108];
__device__ short               g_pool3[BATCH * 48 * 54];
__device__ long long           g_S[3 * 48];
__device__ long long           g_SS[3 * 48];
__device__ double              g_thr[3 * 48];
__device__ int                 g_flip[3 * 48];

// ---------------- weight packing + stat zeroing ----------------
__global__ void k_pack_w(const float* __restrict__ w1, const float* __restrict__ w2,
                         const float* __restrict__ w3, const float* __restrict__ wfc) {
    int tid = threadIdx.x;
    for (int idx = tid; idx < 432; idx += blockDim.x) {
        int o = idx / 9, t = idx % 9;
        unsigned m1 = 0;
        for (int c = 0; c < 12; c++) m1 |= (unsigned)(w1[o * 108 + c * 9 + t] > 0.f) << c;
        g_wp1[idx] = (unsigned short)m1;
        unsigned long long m2 = 0ull, m3 = 0ull;
        for (int c = 0; c < 48; c++) {
            m2 |= (unsigned long long)(w2[o * 432 + c * 9 + t] > 0.f) << c;
            m3 |= (unsigned long long)(w3[o * 432 + c * 9 + t] > 0.f) << c;
        }
        g_wp2[idx] = m2;
        g_wp3[idx] = m3;
    }
    for (int idx = tid; idx < 405; idx += blockDim.x) {
        int o = idx / 81, wi = idx % 81;
        unsigned m = 0;
        for (int l = 0; l < 32; l++)
            m |= (unsigned)(wfc[o * 2592 + wi * 32 + l] > 0.f) << l;
        g_wfcp[idx] = m;
    }
    for (int idx = tid; idx < 144; idx += blockDim.x) { g_S[idx] = 0; g_SS[idx] = 0; }
}

// ---------------- binarize + pack x; writes xb1 ----------------
__global__ void k_pack_x(const float* __restrict__ x, float* __restrict__ out) {
    int idx = blockIdx.x * blockDim.x + threadIdx.x;
    if (idx >= BATCH * 180) return;
    int b = idx / 180, p = idx % 180;
    const float* xb = x + (size_t)b * 2160 + p;
    float* ob = out + XB1_OFF + (size_t)b * 2160 + p;
    unsigned m = 0;
#pragma unroll
    for (int c = 0; c < 12; c++) {
        bool bit = xb[c * 180] > 0.f;
        ob[c * 180] = bit ? 1.f : -1.f;
        m |= (unsigned)bit << c;
    }
    g_xp1[idx] = (unsigned short)m;
}

// ---------------- conv1 (pad1) + maxpool(2,1) + stats ----------------
__global__ void k_conv1(void) {
    __shared__ unsigned short s_in[180];
    __shared__ unsigned short s_w[432];
    __shared__ signed char s_conv[48 * 180];
    __shared__ int s_sum[48], s_sq[48];
    int b = blockIdx.x, tid = threadIdx.x;
    if (tid < 180) s_in[tid] = g_xp1[b * 180 + tid];
    for (int i = tid; i < 432; i += 256) s_w[i] = g_wp1[i];
    if (tid < 48) { s_sum[tid] = 0; s_sq[tid] = 0; }
    __syncthreads();
    for (int idx = tid; idx < 48 * 180; idx += 256) {
        int o = idx / 180, p = idx % 180, h = p / 15, w = p % 15;
        int acc = 0;
#pragma unroll
        for (int kh = 0; kh < 3; kh++) {
            int ih = h + kh - 1;
            if ((unsigned)ih >= 12u) continue;
#pragma unroll
            for (int kw = 0; kw < 3; kw++) {
                int iw = w + kw - 1;
                if ((unsigned)iw >= 15u) continue;
                acc += 12 - 2 * __popc((unsigned)(s_in[ih * 15 + iw] ^ s_w[o * 9 + kh * 3 + kw]));
            }
        }
        s_conv[idx] = (signed char)acc;
    }
    __syncthreads();
    for (int idx = tid; idx < 48 * 154; idx += 256) {
        int o = idx / 154, p = idx % 154, i = p / 14, j = p % 14;
        const signed char* base = s_conv + o * 180 + i * 15 + j;
        int m = max(max((int)base[0], (int)base[1]), max((int)base[15], (int)base[16]));
        g_pool1[(size_t)b * 7392 + idx] = (signed char)m;
        atomicAdd(&s_sum[o], m);
        atomicAdd(&s_sq[o], m * m);
    }
    __syncthreads();
    if (tid < 48) {
        atomicAdd((unsigned long long*)&g_S[tid], (unsigned long long)(long long)s_sum[tid]);
        atomicAdd((unsigned long long*)&g_SS[tid], (unsigned long long)(long long)s_sq[tid]);
    }
}

// ---------------- BN -> threshold in integer domain ----------------
__global__ void k_thresh(int level, const float* __restrict__ gg, const float* __restrict__ bb, double N) {
    int c = threadIdx.x;
    if (c >= 48) return;
    double S = (double)g_S[level * 48 + c];
    double SS = (double)g_SS[level * 48 + c];
    double mean = S / N;
    double var = SS / N - mean * mean;
    double sd = sqrt(var + 1e-5);
    double g = (double)gg[c], b = (double)bb[c];
    // sign(BN) > 0  <=>  g>0 ? h > thr : h < thr,  thr = mean - b*sd/g
    g_thr[level * 48 + c] = mean - b * sd / g;
    g_flip[level * 48 + c] = (g < 0.0);
}

// ---------------- threshold pool1 -> xb2 floats + packed bits ----------------
__global__ void k_apply1(float* __restrict__ out) {
    __shared__ double s_thr[48];
    __shared__ int s_flip[48];
    if (threadIdx.x < 48) { s_thr[threadIdx.x] = g_thr[threadIdx.x]; s_flip[threadIdx.x] = g_flip[threadIdx.x]; }
    __syncthreads();
    int idx = blockIdx.x * blockDim.x + threadIdx.x;
    if (idx >= BATCH * 154) return;
    int b = idx / 154, p = idx % 154;
    const signed char* pin = g_pool1 + (size_t)b * 7392 + p;
    float* po = out + XB2_OFF + (size_t)b * 7392 + p;
    unsigned long long m = 0ull;
#pragma unroll
    for (int c = 0; c < 48; c++) {
        double v = (double)pin[c * 154];
        bool bit = s_flip[c] ? (v < s_thr[c]) : (v > s_thr[c]);
        po[c * 154] = bit ? 1.f : -1.f;
        m |= (unsigned long long)bit << c;
    }
    g_xp2[idx] = m;
}

// ---------------- conv2 (pad0) + stats ----------------
__global__ void k_conv2(void) {
    __shared__ unsigned long long s_in[154];
    __shared__ unsigned long long s_w[432];
    __shared__ int s_sum[48], s_sq[48];
    int b = blockIdx.x, tid = threadIdx.x;
    if (tid < 154) s_in[tid] = g_xp2[b * 154 + tid];
    for (int i = tid; i < 432; i += 256) s_w[i] = g_wp2[i];
    if (tid < 48) { s_sum[tid] = 0; s_sq[tid] = 0; }
    __syncthreads();
    for (int idx = tid; idx < 48 * 108; idx += 256) {
        int o = idx / 108, p = idx % 108, h = p / 12, w = p % 12;
        int pc = 0;
#pragma unroll
        for (int kh = 0; kh < 3; kh++)
#pragma unroll
            for (int kw = 0; kw < 3; kw++)
                pc += __popcll(s_in[(h + kh) * 14 + (w + kw)] ^ s_w[o * 9 + kh * 3 + kw]);
        int val = 432 - 2 * pc;
        g_conv2[(size_t)b * 5184 + idx] = (short)val;
        atomicAdd(&s_sum[o], val);
        atomicAdd(&s_sq[o], val * val);
    }
    __syncthreads();
    if (tid < 48) {
        atomicAdd((unsigned long long*)&g_S[48 + tid], (unsigned long long)(long long)s_sum[tid]);
        atomicAdd((unsigned long long*)&g_SS[48 + tid], (unsigned long long)(long long)s_sq[tid]);
    }
}

// ---------------- threshold conv2 -> xb3 floats + packed bits ----------------
__global__ void k_apply2(float* __restrict__ out) {
    __shared__ double s_thr[48];
    __shared__ int s_flip[48];
    if (threadIdx.x < 48) { s_thr[threadIdx.x] = g_thr[48 + threadIdx.x]; s_flip[threadIdx.x] = g_flip[48 + threadIdx.x]; }
    __syncthreads();
    int idx = blockIdx.x * blockDim.x + threadIdx.x;
    if (idx >= BATCH * 108) return;
    int b = idx / 108, p = idx % 108;
    const short* pin = g_conv2 + (size_t)b * 5184 + p;
    float* po = out + XB3_OFF + (size_t)b * 5184 + p;
    unsigned long long m = 0ull;
#pragma unroll
    for (int c = 0; c < 48; c++) {
        double v = (double)pin[c * 108];
        bool bit = s_flip[c] ? (v < s_thr[c]) : (v > s_thr[c]);
        po[c * 108] = bit ? 1.f : -1.f;
        m |= (unsigned long long)bit << c;
    }
    g_xp3[idx] = m;
}

// ---------------- conv3 (pad0) + maxpool(2,1) + stats ----------------
__global__ void k_conv3(void) {
    __shared__ unsigned long long s_in[108];
    __shared__ unsigned long long s_w[432];
    __shared__ short s_conv[48 * 70];
    __shared__ int s_sum[48], s_sq[48];
    int b = blockIdx.x, tid = threadIdx.x;
    if (tid < 108) s_in[tid] = g_xp3[b * 108 + tid];
    for (int i = tid; i < 432; i += 256) s_w[i] = g_wp3[i];
    if (tid < 48) { s_sum[tid] = 0; s_sq[tid] = 0; }
    __syncthreads();
    for (int idx = tid; idx < 48 * 70; idx += 256) {
        int o = idx / 70, p = idx % 70, h = p / 10, w = p % 10;
        int pc = 0;
#pragma unroll
        for (int kh = 0; kh < 3; kh++)
#pragma unroll
            for (int kw = 0; kw < 3; kw++)
                pc += __popcll(s_in[(h + kh) * 12 + (w + kw)] ^ s_w[o * 9 + kh * 3 + kw]);
        s_conv[idx] = (short)(432 - 2 * pc);
    }
    __syncthreads();
    for (int idx = tid; idx < 48 * 54; idx += 256) {
        int o = idx / 54, p = idx % 54, i = p / 9, j = p % 9;
        const short* base = s_conv + o * 70 + i * 10 + j;
        int m = max(max((int)base[0], (int)base[1]), max((int)base[10], (int)base[11]));
        g_pool3[(size_t)b * 2592 + idx] = (short)m;
        atomicAdd(&s_sum[o], m);
        atomicAdd(&s_sq[o], m * m);
    }
    __syncthreads();
    if (tid < 48) {
        atomicAdd((unsigned long long*)&g_S[96 + tid], (unsigned long long)(long long)s_sum[tid]);
        atomicAdd((unsigned long long*)&g_SS[96 + tid], (unsigned long long)(long long)s_sq[tid]);
    }
}

// ---------------- final: threshold -> fb floats + packed; FC via popcount ----------------
__global__ void k_final(float* __restrict__ out) {
    __shared__ unsigned s_fb[81];
    __shared__ unsigned s_wfc[405];
    __shared__ double s_thr[48];
    __shared__ int s_flip[48];
    int b = blockIdx.x, tid = threadIdx.x;
    int lane = tid & 31, wid = tid >> 5;
    if (tid < 48) { s_thr[tid] = g_thr[96 + tid]; s_flip[tid] = g_flip[96 + tid]; }
    for (int i = tid; i < 405; i += 256) s_wfc[i] = g_wfcp[i];
    __syncthreads();
    for (int i = wid; i < 81; i += 8) {
        int k = i * 32 + lane;          // k in [0,2592): 81*32 == 2592 exactly
        int c = k / 54;
        double v = (double)g_pool3[(size_t)b * 2592 + k];
        bool bit = s_flip[c] ? (v < s_thr[c]) : (v > s_thr[c]);
        out[FB_OFF + (size_t)b * 2592 + k] = bit ? 1.f : -1.f;
        unsigned wmask = __ballot_sync(0xffffffffu, bit);
        if (lane == 0) s_fb[i] = wmask;
    }
    __syncthreads();
    if (wid < 5) {
        int mm = 0;
        for (int l = lane; l < 81; l += 32)
            mm += __popc(s_fb[l] ^ s_wfc[wid * 81 + l]);
        mm = __reduce_add_sync(0xffffffffu, mm);
        if (lane == 0) out[(size_t)b * 5 + wid] = (float)(2592 - 2 * mm);
    }
}

// ---------------- launcher ----------------
extern "C" void kernel_launch(void* const* d_in, const int* in_sizes, int n_in,
                              void* d_out, int out_size) {
    const float* x   = (const float*)d_in[0];
    const float* w1  = (const float*)d_in[1];
    const float* g1  = (const float*)d_in[2];
    const float* b1  = (const float*)d_in[3];
    const float* w2  = (const float*)d_in[4];
    const float* g2  = (const float*)d_in[5];
    const float* b2  = (const float*)d_in[6];
    const float* w3  = (const float*)d_in[7];
    const float* g3  = (const float*)d_in[8];
    const float* b3  = (const float*)d_in[9];
    const float* wfc = (const float*)d_in[10];
    float* out = (float*)d_out;

    k_pack_w<<<1, 512>>>(w1, w2, w3, wfc);
    k_pack_x<<<(BATCH * 180 + 255) / 256, 256>>>(x, out);
    k_conv1<<<BATCH, 256>>>();
    k_thresh<<<1, 64>>>(0, g1, b1, (double)(BATCH * 154));
    k_apply1<<<(BATCH * 154 + 255) / 256, 256>>>(out);
    k_conv2<<<BATCH, 256>>>();
    k_thresh<<<1, 64>>>(1, g2, b2, (double)(BATCH * 108));
    k_apply2<<<(BATCH * 108 + 255) / 256, 256>>>(out);
    k_conv3<<<BATCH, 256>>>();
    k_thresh<<<1, 64>>>(2, g3, b3, (double)(BATCH * 54));
    k_final<<<BATCH, 256>>>(out);
}

// round 5
// speedup vs baseline: 1.7692x; 1.7692x over previous
#include <cuda_runtime.h>
#include <math.h>

// Binarized AlexNet_OWT pipeline, all-integer / XNOR-popcount formulation.
// R5: warp-owns-channel stats (no same-address shared atomics), register
// weights, integer thresholds, k_thresh folded into apply/final kernels.

#define BATCH 4096

#define OUT_OFF 0u
#define XB1_OFF 20480u
#define XB2_OFF 8867840u
#define XB3_OFF 39145472u
#define FB_OFF  60379136u

// ---------------- scratch (static __device__; no allocations) ----------------
__device__ unsigned short      g_xp1[BATCH * 180];        // packed input bits (12 ch)
__device__ unsigned short      g_wp1[48 * 9];
__device__ unsigned long long  g_wp2[48 * 9];
__device__ unsigned long long  g_wp3[48 * 9];
__device__ unsigned int        g_wfcp[5 * 81];
__device__ signed char         g_pool1[BATCH * 48 * 154]; // |v| <= 108
__device__ unsigned long long  g_xp2[BATCH * 154];
__device__ short               g_conv2[BATCH * 48 * 108]; // |v| <= 432
__device__ unsigned long long  g_xp3[BATCH * 108];
__device__ short               g_pool3[BATCH * 48 * 54];
__device__ long long           g_S[3 * 48];
__device__ long long           g_SS[3 * 48];

// ---------------- weight packing + stat zeroing ----------------
__global__ void k_pack_w(const float* __restrict__ w1, const float* __restrict__ w2,
                         const float* __restrict__ w3, const float* __restrict__ wfc) {
    int tid = threadIdx.x;
    for (int idx = tid; idx < 432; idx += blockDim.x) {
        int o = idx / 9, t = idx % 9;
        unsigned m1 = 0;
        for (int c = 0; c < 12; c++) m1 |= (unsigned)(w1[o * 108 + c * 9 + t] > 0.f) << c;
        g_wp1[idx] = (unsigned short)m1;
        unsigned long long m2 = 0ull, m3 = 0ull;
        for (int c = 0; c < 48; c++) {
            m2 |= (unsigned long long)(w2[o * 432 + c * 9 + t] > 0.f) << c;
            m3 |= (unsigned long long)(w3[o * 432 + c * 9 + t] > 0.f) << c;
        }
        g_wp2[idx] = m2;
        g_wp3[idx] = m3;
    }
    for (int idx = tid; idx < 405; idx += blockDim.x) {
        int o = idx / 81, wi = idx % 81;
        unsigned m = 0;
        for (int l = 0; l < 32; l++)
            m |= (unsigned)(wfc[o * 2592 + wi * 32 + l] > 0.f) << l;
        g_wfcp[idx] = m;
    }
    for (int idx = tid; idx < 144; idx += blockDim.x) { g_S[idx] = 0; g_SS[idx] = 0; }
}

// ---------------- binarize + pack x; writes xb1 ----------------
__global__ void k_pack_x(const float* __restrict__ x, float* __restrict__ out) {
    int idx = blockIdx.x * blockDim.x + threadIdx.x;
    if (idx >= BATCH * 180) return;
    int b = idx / 180, p = idx % 180;
    const float* xb = x + (size_t)b * 2160 + p;
    float* ob = out + XB1_OFF + (size_t)b * 2160 + p;
    unsigned m = 0;
#pragma unroll
    for (int c = 0; c < 12; c++) {
        bool bit = xb[c * 180] > 0.f;
        ob[c * 180] = bit ? 1.f : -1.f;
        m |= (unsigned)bit << c;
    }
    g_xp1[idx] = (unsigned short)m;
}

// helper: compute integer threshold for channel c of level.
// sign(BN(v)) > 0  <=>  (g>=0 ? v > ti : v < ti)
__device__ __forceinline__ void compute_thresh(int level, int c, double N,
                                               const float* gg, const float* bb,
                                               int* s_ti, int* s_flip) {
    double S = (double)g_S[level * 48 + c];
    double SS = (double)g_SS[level * 48 + c];
    double mean = S / N;
    double var = SS / N - mean * mean;
    double sd = sqrt(var + 1e-5);
    double g = (double)gg[c], b = (double)bb[c];
    double thr = mean - b * sd / g;
    if (g >= 0.0) { s_ti[c] = (int)floor(thr); s_flip[c] = 0; }
    else          { s_ti[c] = (int)ceil(thr);  s_flip[c] = 1; }
}

// ---------------- conv1 (pad1) + maxpool(2,1) + stats ----------------
__global__ void k_conv1(void) {
    __shared__ unsigned short s_in[180];
    __shared__ unsigned short s_w[432];
    __shared__ signed char s_conv[48 * 180];
    __shared__ int s_sum[48], s_sq[48];
    int b = blockIdx.x, tid = threadIdx.x;
    int lane = tid & 31, wid = tid >> 5;
    if (tid < 180) s_in[tid] = g_xp1[b * 180 + tid];
    for (int i = tid; i < 432; i += 256) s_w[i] = g_wp1[i];
    __syncthreads();

    // compute conv: warp owns channels wid, wid+8, ...
    for (int o = wid; o < 48; o += 8) {
        unsigned rw[9];
#pragma unroll
        for (int t = 0; t < 9; t++) rw[t] = s_w[o * 9 + t];
        for (int p = lane; p < 180; p += 32) {
            int h = p / 15, w = p % 15;
            int acc;
            if ((unsigned)(h - 1) <= 9u && (unsigned)(w - 1) <= 12u) {
                int base = (h - 1) * 15 + (w - 1);
                int pc = __popc((unsigned)(s_in[base +  0] ^ rw[0]))
                       + __popc((unsigned)(s_in[base +  1] ^ rw[1]))
                       + __popc((unsigned)(s_in[base +  2] ^ rw[2]))
                       + __popc((unsigned)(s_in[base + 15] ^ rw[3]))
                       + __popc((unsigned)(s_in[base + 16] ^ rw[4]))
                       + __popc((unsigned)(s_in[base + 17] ^ rw[5]))
                       + __popc((unsigned)(s_in[base + 30] ^ rw[6]))
                       + __popc((unsigned)(s_in[base + 31] ^ rw[7]))
                       + __popc((unsigned)(s_in[base + 32] ^ rw[8]));
                acc = 108 - 2 * pc;
            } else {
                acc = 0;
#pragma unroll
                for (int kh = 0; kh < 3; kh++) {
                    int ih = h + kh - 1;
                    if ((unsigned)ih >= 12u) continue;
#pragma unroll
                    for (int kw = 0; kw < 3; kw++) {
                        int iw = w + kw - 1;
                        if ((unsigned)iw >= 15u) continue;
                        acc += 12 - 2 * __popc((unsigned)(s_in[ih * 15 + iw] ^ rw[kh * 3 + kw]));
                    }
                }
            }
            s_conv[o * 180 + p] = (signed char)acc;
        }
    }
    __syncthreads();

    // pool + stats: warp owns channel, register accumulation, warp reduce
    for (int o = wid; o < 48; o += 8) {
        int sum = 0, sq = 0;
        for (int p = lane; p < 154; p += 32) {
            int i = p / 14, j = p % 14;
            const signed char* base = s_conv + o * 180 + i * 15 + j;
            int m = max(max((int)base[0], (int)base[1]), max((int)base[15], (int)base[16]));
            g_pool1[(size_t)b * 7392 + o * 154 + p] = (signed char)m;
            sum += m; sq += m * m;
        }
        sum = __reduce_add_sync(0xffffffffu, sum);
        sq  = __reduce_add_sync(0xffffffffu, sq);
        if (lane == 0) { s_sum[o] = sum; s_sq[o] = sq; }
    }
    __syncthreads();
    if (tid < 48) {
        atomicAdd((unsigned long long*)&g_S[tid], (unsigned long long)(long long)s_sum[tid]);
        atomicAdd((unsigned long long*)&g_SS[tid], (unsigned long long)(long long)s_sq[tid]);
    }
}

// ---------------- threshold pool1 -> xb2 floats + packed bits ----------------
__global__ void k_apply1(const float* __restrict__ gg, const float* __restrict__ bb,
                         float* __restrict__ out) {
    __shared__ int s_ti[48];
    __shared__ int s_flip[48];
    if (threadIdx.x < 48)
        compute_thresh(0, threadIdx.x, (double)BATCH * 154.0, gg, bb, s_ti, s_flip);
    __syncthreads();
    int idx = blockIdx.x * blockDim.x + threadIdx.x;
    if (idx >= BATCH * 154) return;
    int b = idx / 154, p = idx % 154;
    const signed char* pin = g_pool1 + (size_t)b * 7392 + p;
    float* po = out + XB2_OFF + (size_t)b * 7392 + p;
    unsigned long long m = 0ull;
#pragma unroll
    for (int c = 0; c < 48; c++) {
        int v = (int)pin[c * 154];
        bool bit = s_flip[c] ? (v < s_ti[c]) : (v > s_ti[c]);
        po[c * 154] = bit ? 1.f : -1.f;
        m |= (unsigned long long)bit << c;
    }
    g_xp2[idx] = m;
}

// ---------------- conv2 (pad0) + stats ----------------
__global__ void k_conv2(void) {
    __shared__ unsigned long long s_in[154];
    __shared__ unsigned long long s_w[432];
    __shared__ int s_sum[48], s_sq[48];
    int b = blockIdx.x, tid = threadIdx.x;
    int lane = tid & 31, wid = tid >> 5;
    if (tid < 154) s_in[tid] = g_xp2[b * 154 + tid];
    for (int i = tid; i < 432; i += 256) s_w[i] = g_wp2[i];
    __syncthreads();
    for (int o = wid; o < 48; o += 8) {
        unsigned long long rw[9];
#pragma unroll
        for (int t = 0; t < 9; t++) rw[t] = s_w[o * 9 + t];
        int sum = 0, sq = 0;
        for (int p = lane; p < 108; p += 32) {
            int h = p / 12, w = p % 12;
            const unsigned long long* in = s_in + h * 14 + w;
            int pc = __popcll(in[ 0] ^ rw[0]) + __popcll(in[ 1] ^ rw[1]) + __popcll(in[ 2] ^ rw[2])
                   + __popcll(in[14] ^ rw[3]) + __popcll(in[15] ^ rw[4]) + __popcll(in[16] ^ rw[5])
                   + __popcll(in[28] ^ rw[6]) + __popcll(in[29] ^ rw[7]) + __popcll(in[30] ^ rw[8]);
            int val = 432 - 2 * pc;
            g_conv2[(size_t)b * 5184 + o * 108 + p] = (short)val;
            sum += val; sq += val * val;
        }
        sum = __reduce_add_sync(0xffffffffu, sum);
        sq  = __reduce_add_sync(0xffffffffu, sq);
        if (lane == 0) { s_sum[o] = sum; s_sq[o] = sq; }
    }
    __syncthreads();
    if (tid < 48) {
        atomicAdd((unsigned long long*)&g_S[48 + tid], (unsigned long long)(long long)s_sum[tid]);
        atomicAdd((unsigned long long*)&g_SS[48 + tid], (unsigned long long)(long long)s_sq[tid]);
    }
}

// ---------------- threshold conv2 -> xb3 floats + packed bits ----------------
__global__ void k_apply2(const float* __restrict__ gg, const float* __restrict__ bb,
                         float* __restrict__ out) {
    __shared__ int s_ti[48];
    __shared__ int s_flip[48];
    if (threadIdx.x < 48)
        compute_thresh(1, threadIdx.x, (double)BATCH * 108.0, gg, bb, s_ti, s_flip);
    __syncthreads();
    int idx = blockIdx.x * blockDim.x + threadIdx.x;
    if (idx >= BATCH * 108) return;
    int b = idx / 108, p = idx % 108;
    const short* pin = g_conv2 + (size_t)b * 5184 + p;
    float* po = out + XB3_OFF + (size_t)b * 5184 + p;
    unsigned long long m = 0ull;
#pragma unroll
    for (int c = 0; c < 48; c++) {
        int v = (int)pin[c * 108];
        bool bit = s_flip[c] ? (v < s_ti[c]) : (v > s_ti[c]);
        po[c * 108] = bit ? 1.f : -1.f;
        m |= (unsigned long long)bit << c;
    }
    g_xp3[idx] = m;
}

// ---------------- conv3 (pad0) + maxpool(2,1) + stats ----------------
__global__ void k_conv3(void) {
    __shared__ unsigned long long s_in[108];
    __shared__ unsigned long long s_w[432];
    __shared__ short s_conv[48 * 70];
    __shared__ int s_sum[48], s_sq[48];
    int b = blockIdx.x, tid = threadIdx.x;
    int lane = tid & 31, wid = tid >> 5;
    if (tid < 108) s_in[tid] = g_xp3[b * 108 + tid];
    for (int i = tid; i < 432; i += 256) s_w[i] = g_wp3[i];
    __syncthreads();
    for (int o = wid; o < 48; o += 8) {
        unsigned long long rw[9];
#pragma unroll
        for (int t = 0; t < 9; t++) rw[t] = s_w[o * 9 + t];
        for (int p = lane; p < 70; p += 32) {
            int h = p / 10, w = p % 10;
            const unsigned long long* in = s_in + h * 12 + w;
            int pc = __popcll(in[ 0] ^ rw[0]) + __popcll(in[ 1] ^ rw[1]) + __popcll(in[ 2] ^ rw[2])
                   + __popcll(in[12] ^ rw[3]) + __popcll(in[13] ^ rw[4]) + __popcll(in[14] ^ rw[5])
                   + __popcll(in[24] ^ rw[6]) + __popcll(in[25] ^ rw[7]) + __popcll(in[26] ^ rw[8]);
            s_conv[o * 70 + p] = (short)(432 - 2 * pc);
        }
    }
    __syncthreads();
    for (int o = wid; o < 48; o += 8) {
        int sum = 0, sq = 0;
        for (int p = lane; p < 54; p += 32) {
            int i = p / 9, j = p % 9;
            const short* base = s_conv + o * 70 + i * 10 + j;
            int m = max(max((int)base[0], (int)base[1]), max((int)base[10], (int)base[11]));
            g_pool3[(size_t)b * 2592 + o * 54 + p] = (short)m;
            sum += m; sq += m * m;
        }
        sum = __reduce_add_sync(0xffffffffu, sum);
        sq  = __reduce_add_sync(0xffffffffu, sq);
        if (lane == 0) { s_sum[o] = sum; s_sq[o] = sq; }
    }
    __syncthreads();
    if (tid < 48) {
        atomicAdd((unsigned long long*)&g_S[96 + tid], (unsigned long long)(long long)s_sum[tid]);
        atomicAdd((unsigned long long*)&g_SS[96 + tid], (unsigned long long)(long long)s_sq[tid]);
    }
}

// ---------------- final: threshold -> fb floats + packed; FC via popcount ----------------
__global__ void k_final(const float* __restrict__ gg, const float* __restrict__ bb,
                        float* __restrict__ out) {
    __shared__ unsigned s_fb[81];
    __shared__ unsigned s_wfc[405];
    __shared__ int s_ti[48];
    __shared__ int s_flip[48];
    int b = blockIdx.x, tid = threadIdx.x;
    int lane = tid & 31, wid = tid >> 5;
    if (tid < 48)
        compute_thresh(2, tid, (double)BATCH * 54.0, gg, bb, s_ti, s_flip);
    for (int i = tid; i < 405; i += 256) s_wfc[i] = g_wfcp[i];
    __syncthreads();
    for (int i = wid; i < 81; i += 8) {
        int k = i * 32 + lane;          // k in [0,2592): 81*32 == 2592 exactly
        int c = k / 54;
        int v = (int)g_pool3[(size_t)b * 2592 + k];
        bool bit = s_flip[c] ? (v < s_ti[c]) : (v > s_ti[c]);
        out[FB_OFF + (size_t)b * 2592 + k] = bit ? 1.f : -1.f;
        unsigned wmask = __ballot_sync(0xffffffffu, bit);
        if (lane == 0) s_fb[i] = wmask;
    }
    __syncthreads();
    if (wid < 5) {
        int mm = 0;
        for (int l = lane; l < 81; l += 32)
            mm += __popc(s_fb[l] ^ s_wfc[wid * 81 + l]);
        mm = __reduce_add_sync(0xffffffffu, mm);
        if (lane == 0) out[(size_t)b * 5 + wid] = (float)(2592 - 2 * mm);
    }
}

// ---------------- launcher ----------------
extern "C" void kernel_launch(void* const* d_in, const int* in_sizes, int n_in,
                              void* d_out, int out_size) {
    const float* x   = (const float*)d_in[0];
    const float* w1  = (const float*)d_in[1];
    const float* g1  = (const float*)d_in[2];
    const float* b1  = (const float*)d_in[3];
    const float* w2  = (const float*)d_in[4];
    const float* g2  = (const float*)d_in[5];
    const float* b2  = (const float*)d_in[6];
    const float* w3  = (const float*)d_in[7];
    const float* g3  = (const float*)d_in[8];
    const float* b3  = (const float*)d_in[9];
    const float* wfc = (const float*)d_in[10];
    float* out = (float*)d_out;

    k_pack_w<<<1, 512>>>(w1, w2, w3, wfc);
    k_pack_x<<<(BATCH * 180 + 255) / 256, 256>>>(x, out);
    k_conv1<<<BATCH, 256>>>();
    k_apply1<<<(BATCH * 154 + 255) / 256, 256>>>(g1, b1, out);
    k_conv2<<<BATCH, 256>>>();
    k_apply2<<<(BATCH * 108 + 255) / 256, 256>>>(g2, b2, out);
    k_conv3<<<BATCH, 256>>>();
    k_final<<<BATCH, 256>>>(g3, b3, out);
}

// round 7
// speedup vs baseline: 1.8783x; 1.0616x over previous
#include <cuda_runtime.h>
#include <math.h>

// Binarized AlexNet_OWT, XNOR-popcount formulation.
// R6: logic kernels emit packed bitmasks only; dedicated expand kernels
// stream bits -> +-1.0f with aligned STG.128. conv2/pool3 intermediates in
// half-domain int8 (u = 216 - popcount), stats rescaled exactly.

#define BATCH 4096

#define XB1_OFF 20480u
#define XB2_OFF 8867840u
#define XB3_OFF 39145472u
#define FB_OFF  60379136u

// ---------------- scratch (static __device__; no allocations) ----------------
__device__ unsigned short      g_xp1[BATCH * 180];        // packed input bits (12 ch)
__device__ unsigned short      g_wp1[48 * 9];
__device__ unsigned long long  g_wp2[48 * 9];
__device__ unsigned long long  g_wp3[48 * 9];
__device__ unsigned int        g_wfcp[5 * 81];
__device__ signed char         g_pool1[BATCH * 48 * 154]; // full-domain, |v|<=108
__device__ unsigned long long  g_xp2[BATCH * 154];
__device__ signed char         g_conv2[BATCH * 48 * 108]; // half-domain u=216-pc
__device__ unsigned long long  g_xp3[BATCH * 108];
__device__ signed char         g_pool3[BATCH * 48 * 54];  // half-domain
__device__ unsigned int        g_fbp[BATCH * 81];
__device__ long long           g_S[3 * 48];
__device__ long long           g_SS[3 * 48];

// ---------------- weight packing + stat zeroing ----------------
__global__ void k_pack_w(const float* __restrict__ w1, const float* __restrict__ w2,
                         const float* __restrict__ w3, const float* __restrict__ wfc) {
    int tid = threadIdx.x;
    for (int idx = tid; idx < 432; idx += blockDim.x) {
        int o = idx / 9, t = idx % 9;
        unsigned m1 = 0;
        for (int c = 0; c < 12; c++) m1 |= (unsigned)(w1[o * 108 + c * 9 + t] > 0.f) << c;
        g_wp1[idx] = (unsigned short)m1;
        unsigned long long m2 = 0ull, m3 = 0ull;
        for (int c = 0; c < 48; c++) {
            m2 |= (unsigned long long)(w2[o * 432 + c * 9 + t] > 0.f) << c;
            m3 |= (unsigned long long)(w3[o * 432 + c * 9 + t] > 0.f) << c;
        }
        g_wp2[idx] = m2;
        g_wp3[idx] = m3;
    }
    for (int idx = tid; idx < 405; idx += blockDim.x) {
        int o = idx / 81, wi = idx % 81;
        unsigned m = 0;
        for (int l = 0; l < 32; l++)
            m |= (unsigned)(wfc[o * 2592 + wi * 32 + l] > 0.f) << l;
        g_wfcp[idx] = m;
    }
    for (int idx = tid; idx < 144; idx += blockDim.x) { g_S[idx] = 0; g_SS[idx] = 0; }
}

// ---------------- binarize + pack x (float4 reads, u64 packed writes) --------
// thread handles 4 consecutive spatial positions of one image.
__global__ void k_pack_x(const float* __restrict__ x) {
    int idx = blockIdx.x * blockDim.x + threadIdx.x;   // [0, BATCH*45)
    if (idx >= BATCH * 45) return;
    int b = idx / 45, q = idx % 45;                    // q = p/4
    const float4* xb = (const float4*)(x + (size_t)b * 2160) + q;
    unsigned short m[4] = {0, 0, 0, 0};
#pragma unroll
    for (int c = 0; c < 12; c++) {
        float4 v = xb[c * 45];
        m[0] |= (unsigned short)((v.x > 0.f) << c);
        m[1] |= (unsigned short)((v.y > 0.f) << c);
        m[2] |= (unsigned short)((v.z > 0.f) << c);
        m[3] |= (unsigned short)((v.w > 0.f) << c);
    }
    unsigned long long pk = (unsigned long long)m[0]
                          | ((unsigned long long)m[1] << 16)
                          | ((unsigned long long)m[2] << 32)
                          | ((unsigned long long)m[3] << 48);
    ((unsigned long long*)g_xp1)[idx] = pk;
}

// helper: integer threshold for channel c of level, values stored as v/scale.
// sign(BN(v)) > 0  <=>  (g>=0 ? u > ti : u < ti), u = v/scale.
__device__ __forceinline__ void compute_thresh(int level, int c, double N, double scale,
                                               const float* gg, const float* bb,
                                               int* s_ti, int* s_flip) {
    double S = scale * (double)g_S[level * 48 + c];          // v-domain sum
    double SS = scale * scale * (double)g_SS[level * 48 + c];// v-domain sumsq
    double mean = S / N;
    double var = SS / N - mean * mean;
    double sd = sqrt(var + 1e-5);
    double g = (double)gg[c], b = (double)bb[c];
    double thr_u = (mean - b * sd / g) / scale;
    if (g >= 0.0) { s_ti[c] = (int)floor(thr_u); s_flip[c] = 0; }
    else          { s_ti[c] = (int)ceil(thr_u);  s_flip[c] = 1; }
}

// ---------------- conv1 (pad1) + maxpool(2,1) + stats ----------------
__global__ void k_conv1(void) {
    __shared__ unsigned short s_in[180];
    __shared__ unsigned short s_w[432];
    __shared__ signed char s_conv[48 * 180];
    __shared__ int s_sum[48], s_sq[48];
    int b = blockIdx.x, tid = threadIdx.x;
    int lane = tid & 31, wid = tid >> 5;
    if (tid < 180) s_in[tid] = g_xp1[b * 180 + tid];
    for (int i = tid; i < 432; i += 256) s_w[i] = g_wp1[i];
    __syncthreads();

    for (int o = wid; o < 48; o += 8) {
        unsigned rw[9];
#pragma unroll
        for (int t = 0; t < 9; t++) rw[t] = s_w[o * 9 + t];
        for (int p = lane; p < 180; p += 32) {
            int h = p / 15, w = p % 15;
            int acc;
            if ((unsigned)(h - 1) <= 9u && (unsigned)(w - 1) <= 12u) {
                int base = (h - 1) * 15 + (w - 1);
                int pc = __popc((unsigned)(s_in[base +  0] ^ rw[0]))
                       + __popc((unsigned)(s_in[base +  1] ^ rw[1]))
                       + __popc((unsigned)(s_in[base +  2] ^ rw[2]))
                       + __popc((unsigned)(s_in[base + 15] ^ rw[3]))
                       + __popc((unsigned)(s_in[base + 16] ^ rw[4]))
                       + __popc((unsigned)(s_in[base + 17] ^ rw[5]))
                       + __popc((unsigned)(s_in[base + 30] ^ rw[6]))
                       + __popc((unsigned)(s_in[base + 31] ^ rw[7]))
                       + __popc((unsigned)(s_in[base + 32] ^ rw[8]));
                acc = 108 - 2 * pc;
            } else {
                acc = 0;
#pragma unroll
                for (int kh = 0; kh < 3; kh++) {
                    int ih = h + kh - 1;
                    if ((unsigned)ih >= 12u) continue;
#pragma unroll
                    for (int kw = 0; kw < 3; kw++) {
                        int iw = w + kw - 1;
                        if ((unsigned)iw >= 15u) continue;
                        acc += 12 - 2 * __popc((unsigned)(s_in[ih * 15 + iw] ^ rw[kh * 3 + kw]));
                    }
                }
            }
            s_conv[o * 180 + p] = (signed char)acc;
        }
    }
    __syncthreads();

    for (int o = wid; o < 48; o += 8) {
        int sum = 0, sq = 0;
        for (int p = lane; p < 154; p += 32) {
            int i = p / 14, j = p % 14;
            const signed char* base = s_conv + o * 180 + i * 15 + j;
            int m = max(max((int)base[0], (int)base[1]), max((int)base[15], (int)base[16]));
            g_pool1[(size_t)b * 7392 + o * 154 + p] = (signed char)m;
            sum += m; sq += m * m;
        }
        sum = __reduce_add_sync(0xffffffffu, sum);
        sq  = __reduce_add_sync(0xffffffffu, sq);
        if (lane == 0) { s_sum[o] = sum; s_sq[o] = sq; }
    }
    __syncthreads();
    if (tid < 48) {
        atomicAdd((unsigned long long*)&g_S[tid], (unsigned long long)(long long)s_sum[tid]);
        atomicAdd((unsigned long long*)&g_SS[tid], (unsigned long long)(long long)s_sq[tid]);
    }
}

// ---------------- threshold pool1 -> packed xp2 bits ----------------
__global__ void k_thresh1(const float* __restrict__ gg, const float* __restrict__ bb) {
    __shared__ int s_ti[48];
    __shared__ int s_flip[48];
    if (threadIdx.x < 48)
        compute_thresh(0, threadIdx.x, (double)BATCH * 154.0, 1.0, gg, bb, s_ti, s_flip);
    __syncthreads();
    int idx = blockIdx.x * blockDim.x + threadIdx.x;
    if (idx >= BATCH * 154) return;
    int b = idx / 154, p = idx % 154;
    const signed char* pin = g_pool1 + (size_t)b * 7392 + p;
    unsigned long long m = 0ull;
#pragma unroll
    for (int c = 0; c < 48; c++) {
        int v = (int)pin[c * 154];
        bool bit = s_flip[c] ? (v < s_ti[c]) : (v > s_ti[c]);
        m |= (unsigned long long)bit << c;
    }
    g_xp2[idx] = m;
}

// ---------------- conv2 (pad0) + stats (half-domain u = 216 - pc) ------------
__global__ void k_conv2(void) {
    __shared__ unsigned long long s_in[154];
    __shared__ unsigned long long s_w[432];
    __shared__ int s_sum[48], s_sq[48];
    int b = blockIdx.x, tid = threadIdx.x;
    int lane = tid & 31, wid = tid >> 5;
    if (tid < 154) s_in[tid] = g_xp2[b * 154 + tid];
    for (int i = tid; i < 432; i += 256) s_w[i] = g_wp2[i];
    __syncthreads();
    for (int o = wid; o < 48; o += 8) {
        unsigned long long rw[9];
#pragma unroll
        for (int t = 0; t < 9; t++) rw[t] = s_w[o * 9 + t];
        int sum = 0, sq = 0;
        for (int p = lane; p < 108; p += 32) {
            int h = p / 12, w = p % 12;
            const unsigned long long* in = s_in + h * 14 + w;
            int pc = __popcll(in[ 0] ^ rw[0]) + __popcll(in[ 1] ^ rw[1]) + __popcll(in[ 2] ^ rw[2])
                   + __popcll(in[14] ^ rw[3]) + __popcll(in[15] ^ rw[4]) + __popcll(in[16] ^ rw[5])
                   + __popcll(in[28] ^ rw[6]) + __popcll(in[29] ^ rw[7]) + __popcll(in[30] ^ rw[8]);
            int u = 216 - pc;                       // half of (432 - 2pc)
            g_conv2[(size_t)b * 5184 + o * 108 + p] = (signed char)u;
            sum += u; sq += u * u;
        }
        sum = __reduce_add_sync(0xffffffffu, sum);
        sq  = __reduce_add_sync(0xffffffffu, sq);
        if (lane == 0) { s_sum[o] = sum; s_sq[o] = sq; }
    }
    __syncthreads();
    if (tid < 48) {
        atomicAdd((unsigned long long*)&g_S[48 + tid], (unsigned long long)(long long)s_sum[tid]);
        atomicAdd((unsigned long long*)&g_SS[48 + tid], (unsigned long long)(long long)s_sq[tid]);
    }
}

// ---------------- threshold conv2 -> packed xp3 bits ----------------
__global__ void k_thresh2(const float* __restrict__ gg, const float* __restrict__ bb) {
    __shared__ int s_ti[48];
    __shared__ int s_flip[48];
    if (threadIdx.x < 48)
        compute_thresh(1, threadIdx.x, (double)BATCH * 108.0, 2.0, gg, bb, s_ti, s_flip);
    __syncthreads();
    int idx = blockIdx.x * blockDim.x + threadIdx.x;
    if (idx >= BATCH * 108) return;
    int b = idx / 108, p = idx % 108;
    const signed char* pin = g_conv2 + (size_t)b * 5184 + p;
    unsigned long long m = 0ull;
#pragma unroll
    for (int c = 0; c < 48; c++) {
        int v = (int)pin[c * 108];
        bool bit = s_flip[c] ? (v < s_ti[c]) : (v > s_ti[c]);
        m |= (unsigned long long)bit << c;
    }
    g_xp3[idx] = m;
}

// ---------------- conv3 (pad0) + maxpool(2,1) + stats (half-domain) ----------
__global__ void k_conv3(void) {
    __shared__ unsigned long long s_in[108];
    __shared__ unsigned long long s_w[432];
    __shared__ signed char s_conv[48 * 70];
    __shared__ int s_sum[48], s_sq[48];
    int b = blockIdx.x, tid = threadIdx.x;
    int lane = tid & 31, wid = tid >> 5;
    if (tid < 108) s_in[tid] = g_xp3[b * 108 + tid];
    for (int i = tid; i < 432; i += 256) s_w[i] = g_wp3[i];
    __syncthreads();
    for (int o = wid; o < 48; o += 8) {
        unsigned long long rw[9];
#pragma unroll
        for (int t = 0; t < 9; t++) rw[t] = s_w[o * 9 + t];
        for (int p = lane; p < 70; p += 32) {
            int h = p / 10, w = p % 10;
            const unsigned long long* in = s_in + h * 12 + w;
            int pc = __popcll(in[ 0] ^ rw[0]) + __popcll(in[ 1] ^ rw[1]) + __popcll(in[ 2] ^ rw[2])
                   + __popcll(in[12] ^ rw[3]) + __popcll(in[13] ^ rw[4]) + __popcll(in[14] ^ rw[5])
                   + __popcll(in[24] ^ rw[6]) + __popcll(in[25] ^ rw[7]) + __popcll(in[26] ^ rw[8]);
            s_conv[o * 70 + p] = (signed char)(216 - pc);   // half-domain
        }
    }
    __syncthreads();
    for (int o = wid; o < 48; o += 8) {
        int sum = 0, sq = 0;
        for (int p = lane; p < 54; p += 32) {
            int i = p / 9, j = p % 9;
            const signed char* base = s_conv + o * 70 + i * 10 + j;
            int m = max(max((int)base[0], (int)base[1]), max((int)base[10], (int)base[11]));
            g_pool3[(size_t)b * 2592 + o * 54 + p] = (signed char)m;
            sum += m; sq += m * m;
        }
        sum = __reduce_add_sync(0xffffffffu, sum);
        sq  = __reduce_add_sync(0xffffffffu, sq);
        if (lane == 0) { s_sum[o] = sum; s_sq[o] = sq; }
    }
    __syncthreads();
    if (tid < 48) {
        atomicAdd((unsigned long long*)&g_S[96 + tid], (unsigned long long)(long long)s_sum[tid]);
        atomicAdd((unsigned long long*)&g_SS[96 + tid], (unsigned long long)(long long)s_sq[tid]);
    }
}

// ---------------- final: threshold -> packed fb; FC via popcount -------------
__global__ void k_final(const float* __restrict__ gg, const float* __restrict__ bb,
                        float* __restrict__ out) {
    __shared__ unsigned s_fb[81];
    __shared__ unsigned s_wfc[405];
    __shared__ int s_ti[48];
    __shared__ int s_flip[48];
    int b = blockIdx.x, tid = threadIdx.x;
    int lane = tid & 31, wid = tid >> 5;
    if (tid < 48)
        compute_thresh(2, tid, (double)BATCH * 54.0, 2.0, gg, bb, s_ti, s_flip);
    for (int i = tid; i < 405; i += 256) s_wfc[i] = g_wfcp[i];
    __syncthreads();
    for (int i = wid; i < 81; i += 8) {
        int k = i * 32 + lane;          // 81*32 == 2592 exactly
        int c = k / 54;
        int v = (int)g_pool3[(size_t)b * 2592 + k];
        bool bit = s_flip[c] ? (v < s_ti[c]) : (v > s_ti[c]);
        unsigned wmask = __ballot_sync(0xffffffffu, bit);
        if (lane == 0) { s_fb[i] = wmask; g_fbp[b * 81 + i] = wmask; }
    }
    __syncthreads();
    if (wid < 5) {
        int mm = 0;
        for (int l = lane; l < 81; l += 32)
            mm += __popc(s_fb[l] ^ s_wfc[wid * 81 + l]);
        mm = __reduce_add_sync(0xffffffffu, mm);
        if (lane == 0) out[(size_t)b * 5 + wid] = (float)(2592 - 2 * mm);
    }
}

// ---------------- expand kernels: packed bits -> +-1.0f (STG.128) ------------
__device__ __forceinline__ float bit2f(unsigned b) { return b ? 1.f : -1.f; }

// xb1: [B,12,180], rows of 180 (mult of 4). bit(c,p) = xp1[b*180+p]>>c.
__global__ void k_expand_xb1(float* __restrict__ out) {
    __shared__ unsigned short s_m[180];
    int b = blockIdx.x, tid = threadIdx.x;
    if (tid < 180) s_m[tid] = g_xp1[b * 180 + tid];
    __syncthreads();
    float4* dst = (float4*)(out + XB1_OFF + (size_t)b * 2160);
    for (int f = tid; f < 540; f += 256) {
        int c = f / 45, p = (f % 45) * 4;
        float4 v;
        v.x = bit2f((s_m[p + 0] >> c) & 1u);
        v.y = bit2f((s_m[p + 1] >> c) & 1u);
        v.z = bit2f((s_m[p + 2] >> c) & 1u);
        v.w = bit2f((s_m[p + 3] >> c) & 1u);
        dst[f] = v;
    }
}

// xb2: [B,48,154], rows of 154 (NOT mult of 4): float4 may cross channel rows.
__global__ void k_expand_xb2(float* __restrict__ out) {
    __shared__ unsigned long long s_m[154];
    int b = blockIdx.x, tid = threadIdx.x;
    if (tid < 154) s_m[tid] = g_xp2[b * 154 + tid];
    __syncthreads();
    float4* dst = (float4*)(out + XB2_OFF + (size_t)b * 7392);
    for (int f = tid; f < 1848; f += 256) {
        int e = f * 4;
        int c = e / 154, p = e - c * 154;
        float r[4];
#pragma unroll
        for (int i = 0; i < 4; i++) {
            int pi = p + i, ci = c;
            if (pi >= 154) { pi -= 154; ci += 1; }
            r[i] = bit2f((unsigned)(s_m[pi] >> ci) & 1u);
        }
        dst[f] = make_float4(r[0], r[1], r[2], r[3]);
    }
}

// xb3: [B,48,108], rows of 108 (mult of 4).
__global__ void k_expand_xb3(float* __restrict__ out) {
    __shared__ unsigned long long s_m[108];
    int b = blockIdx.x, tid = threadIdx.x;
    if (tid < 108) s_m[tid] = g_xp3[b * 108 + tid];
    __syncthreads();
    float4* dst = (float4*)(out + XB3_OFF + (size_t)b * 5184);
    for (int f = tid; f < 1296; f += 256) {
        int c = f / 27, p = (f % 27) * 4;
        float4 v;
        v.x = bit2f((unsigned)(s_m[p + 0] >> c) & 1u);
        v.y = bit2f((unsigned)(s_m[p + 1] >> c) & 1u);
        v.z = bit2f((unsigned)(s_m[p + 2] >> c) & 1u);
        v.w = bit2f((unsigned)(s_m[p + 3] >> c) & 1u);
        dst[f] = v;
    }
}

// fb: [B,2592] flat bits; 4-aligned group always within one u32 word.
__global__ void k_expand_fb(float* __restrict__ out) {
    __shared__ unsigned s_m[81];
    int b = blockIdx.x, tid = threadIdx.x;
    if (tid < 81) s_m[tid] = g_fbp[b * 81 + tid];
    __syncthreads();
    float4* dst = (float4*)(out + FB_OFF + (size_t)b * 2592);
    for (int f = tid; f < 648; f += 256) {
        int e = f * 4;
        unsigned w = s_m[e >> 5] >> (e & 31);
        float4 v;
        v.x = bit2f(w & 1u);
        v.y = bit2f((w >> 1) & 1u);
        v.z = bit2f((w >> 2) & 1u);
        v.w = bit2f((w >> 3) & 1u);
        dst[f] = v;
    }
}

// ---------------- launcher ----------------
extern "C" void kernel_launch(void* const* d_in, const int* in_sizes, int n_in,
                              void* d_out, int out_size) {
    const float* x   = (const float*)d_in[0];
    const float* g1  = (const float*)d_in[2];
    const float* b1  = (const float*)d_in[3];
    const float* g2  = (const float*)d_in[5];
    const float* b2  = (const float*)d_in[6];
    const float* g3  = (const float*)d_in[8];
    const float* b3  = (const float*)d_in[9];
    float* out = (float*)d_out;

    k_pack_w<<<1, 512>>>((const float*)d_in[1], (const float*)d_in[4],
                         (const float*)d_in[7], (const float*)d_in[10]);
    k_pack_x<<<(BATCH * 45 + 255) / 256, 256>>>(x);
    k_conv1<<<BATCH, 256>>>();
    k_thresh1<<<(BATCH * 154 + 255) / 256, 256>>>(g1, b1);
    k_conv2<<<BATCH, 256>>>();
    k_thresh2<<<(BATCH * 108 + 255) / 256, 256>>>(g2, b2);
    k_conv3<<<BATCH, 256>>>();
    k_final<<<BATCH, 256>>>(g3, b3, out);
    k_expand_xb1<<<BATCH, 256>>>(out);
    k_expand_xb2<<<BATCH, 256>>>(out);
    k_expand_xb3<<<BATCH, 256>>>(out);
    k_expand_fb<<<BATCH, 256>>>(out);
}

// round 13
// speedup vs baseline: 1.9324x; 1.0288x over previous
#include <cuda_runtime.h>
#include <math.h>

// Binarized AlexNet_OWT, XNOR-popcount formulation.
// R10 = R8 with alignment fix: shared staging buffers declared as uint4
// (16B-aligned) and aliased as signed char* for byte writes.
// Transposed [b][pos][ch] int8 intermediates (coalesced), sign-folded
// thresholds (uniform v' > ti), fused thresh+expand, 8 launches.

#define BATCH 4096

#define XB1_OFF 20480u
#define XB2_OFF 8867840u
#define XB3_OFF 39145472u
#define FB_OFF  60379136u

// ---------------- scratch (static __device__; no allocations) ----------------
__device__ unsigned short      g_xp1[BATCH * 180];
__device__ unsigned short      g_wp1[48 * 9];
__device__ unsigned long long  g_wp2[48 * 9];
__device__ unsigned long long  g_wp3[48 * 9];
__device__ unsigned int        g_wfcp[5 * 81];
__device__ uint4               g_pool1t[BATCH * 462];  // [b][154][48] s8, sign-folded
__device__ unsigned long long  g_xp2[BATCH * 154];
__device__ uint4               g_conv2t[BATCH * 324];  // [b][108][48] s8 half-domain, sign-folded
__device__ unsigned long long  g_xp3[BATCH * 108];
__device__ uint4               g_pool3t[BATCH * 162];  // [b][54][48] s8 half-domain, sign-folded
__device__ long long           g_S[3 * 48];
__device__ long long           g_SS[3 * 48];

// ---------------- weight packing + stat zeroing ----------------
__global__ void k_pack_w(const float* __restrict__ w1, const float* __restrict__ w2,
                         const float* __restrict__ w3, const float* __restrict__ wfc) {
    int tid = threadIdx.x;
    for (int idx = tid; idx < 432; idx += blockDim.x) {
        int o = idx / 9, t = idx % 9;
        unsigned m1 = 0;
        for (int c = 0; c < 12; c++) m1 |= (unsigned)(w1[o * 108 + c * 9 + t] > 0.f) << c;
        g_wp1[idx] = (unsigned short)m1;
        unsigned long long m2 = 0ull, m3 = 0ull;
        for (int c = 0; c < 48; c++) {
            m2 |= (unsigned long long)(w2[o * 432 + c * 9 + t] > 0.f) << c;
            m3 |= (unsigned long long)(w3[o * 432 + c * 9 + t] > 0.f) << c;
        }
        g_wp2[idx] = m2;
        g_wp3[idx] = m3;
    }
    for (int idx = tid; idx < 405; idx += blockDim.x) {
        int o = idx / 81, wi = idx % 81;
        unsigned m = 0;
        for (int l = 0; l < 32; l++)
            m |= (unsigned)(wfc[o * 2592 + wi * 32 + l] > 0.f) << l;
        g_wfcp[idx] = m;
    }
    for (int idx = tid; idx < 144; idx += blockDim.x) { g_S[idx] = 0; g_SS[idx] = 0; }
}

// ---------------- binarize + pack x + write xb1 floats ----------------
__global__ void k_pack_x(const float* __restrict__ x, float* __restrict__ out) {
    int idx = blockIdx.x * blockDim.x + threadIdx.x;   // [0, BATCH*45)
    if (idx >= BATCH * 45) return;
    int b = idx / 45, q = idx % 45;                    // q = p/4
    const float4* xb = (const float4*)(x + (size_t)b * 2160) + q;
    float4* ob = (float4*)(out + XB1_OFF + (size_t)b * 2160) + q;
    unsigned short m[4] = {0, 0, 0, 0};
#pragma unroll
    for (int c = 0; c < 12; c++) {
        float4 v = xb[c * 45];
        bool b0 = v.x > 0.f, b1 = v.y > 0.f, b2 = v.z > 0.f, b3 = v.w > 0.f;
        m[0] |= (unsigned short)(b0 << c);
        m[1] |= (unsigned short)(b1 << c);
        m[2] |= (unsigned short)(b2 << c);
        m[3] |= (unsigned short)(b3 << c);
        ob[c * 45] = make_float4(b0 ? 1.f : -1.f, b1 ? 1.f : -1.f,
                                 b2 ? 1.f : -1.f, b3 ? 1.f : -1.f);
    }
    unsigned long long pk = (unsigned long long)m[0]
                          | ((unsigned long long)m[1] << 16)
                          | ((unsigned long long)m[2] << 32)
                          | ((unsigned long long)m[3] << 48);
    ((unsigned long long*)g_xp1)[idx] = pk;
}

// helper: sign-folded integer threshold for channel c.
// Producers store v' = sgn(g_c)*v; bit = (v' > ti) with ti = floor(sgn*thr).
__device__ __forceinline__ int compute_thresh(int level, int c, double N, double scale,
                                              const float* gg, const float* bb) {
    double S = scale * (double)g_S[level * 48 + c];
    double SS = scale * scale * (double)g_SS[level * 48 + c];
    double mean = S / N;
    double var = SS / N - mean * mean;
    double sd = sqrt(var + 1e-5);
    double g = (double)gg[c], b = (double)bb[c];
    double thr_u = (mean - b * sd / g) / scale;
    return (int)floor(g >= 0.0 ? thr_u : -thr_u);
}

// ---------------- conv1 (pad1) + maxpool(2,1) + stats, transposed out --------
__global__ void k_conv1(const float* __restrict__ gg) {
    __shared__ unsigned short s_in[180];
    __shared__ unsigned short s_w[432];
    __shared__ uint4 s_conv4[(48 * 180 + 15) / 16];     // 16B-aligned byte store
    __shared__ uint4 s_pt4[154 * 3];                    // 154*48 bytes
    __shared__ int s_sum[48], s_sq[48];
    signed char* s_conv = (signed char*)s_conv4;
    signed char* s_pt = (signed char*)s_pt4;
    int b = blockIdx.x, tid = threadIdx.x;
    int lane = tid & 31, wid = tid >> 5;
    if (tid < 180) s_in[tid] = g_xp1[b * 180 + tid];
    for (int i = tid; i < 432; i += 256) s_w[i] = g_wp1[i];
    __syncthreads();

    for (int o = wid; o < 48; o += 8) {
        unsigned rw[9];
#pragma unroll
        for (int t = 0; t < 9; t++) rw[t] = s_w[o * 9 + t];
        for (int p = lane; p < 180; p += 32) {
            int h = p / 15, w = p % 15;
            int acc;
            if ((unsigned)(h - 1) <= 9u && (unsigned)(w - 1) <= 12u) {
                int base = (h - 1) * 15 + (w - 1);
                int pc = __popc((unsigned)(s_in[base +  0] ^ rw[0]))
                       + __popc((unsigned)(s_in[base +  1] ^ rw[1]))
                       + __popc((unsigned)(s_in[base +  2] ^ rw[2]))
                       + __popc((unsigned)(s_in[base + 15] ^ rw[3]))
                       + __popc((unsigned)(s_in[base + 16] ^ rw[4]))
                       + __popc((unsigned)(s_in[base + 17] ^ rw[5]))
                       + __popc((unsigned)(s_in[base + 30] ^ rw[6]))
                       + __popc((unsigned)(s_in[base + 31] ^ rw[7]))
                       + __popc((unsigned)(s_in[base + 32] ^ rw[8]));
                acc = 108 - 2 * pc;
            } else {
                acc = 0;
#pragma unroll
                for (int kh = 0; kh < 3; kh++) {
                    int ih = h + kh - 1;
                    if ((unsigned)ih >= 12u) continue;
#pragma unroll
                    for (int kw = 0; kw < 3; kw++) {
                        int iw = w + kw - 1;
                        if ((unsigned)iw >= 15u) continue;
                        acc += 12 - 2 * __popc((unsigned)(s_in[ih * 15 + iw] ^ rw[kh * 3 + kw]));
                    }
                }
            }
            s_conv[o * 180 + p] = (signed char)acc;
        }
    }
    __syncthreads();

    for (int o = wid; o < 48; o += 8) {
        int neg = (gg[o] < 0.f) ? -1 : 1;
        int sum = 0, sq = 0;
        for (int p = lane; p < 154; p += 32) {
            int i = p / 14, j = p % 14;
            const signed char* base = s_conv + o * 180 + i * 15 + j;
            int m = max(max((int)base[0], (int)base[1]), max((int)base[15], (int)base[16]));
            s_pt[p * 48 + o] = (signed char)(neg * m);
            sum += m; sq += m * m;
        }
        sum = __reduce_add_sync(0xffffffffu, sum);
        sq  = __reduce_add_sync(0xffffffffu, sq);
        if (lane == 0) { s_sum[o] = sum; s_sq[o] = sq; }
    }
    __syncthreads();
    {
        uint4* dp = g_pool1t + (size_t)b * 462;
        for (int i = tid; i < 462; i += 256) dp[i] = s_pt4[i];
    }
    if (tid < 48) {
        atomicAdd((unsigned long long*)&g_S[tid], (unsigned long long)(long long)s_sum[tid]);
        atomicAdd((unsigned long long*)&g_SS[tid], (unsigned long long)(long long)s_sq[tid]);
    }
}

// ---------------- generic: compare 48 sign-folded bytes -> 48-bit mask -------
__device__ __forceinline__ unsigned long long cmp48(const uint4* src, const int* s_ti) {
    uint4 wa = src[0], wb = src[1], wc = src[2];
    unsigned wv[12] = {wa.x, wa.y, wa.z, wa.w, wb.x, wb.y, wb.z, wb.w,
                       wc.x, wc.y, wc.z, wc.w};
    unsigned long long m = 0ull;
#pragma unroll
    for (int j = 0; j < 12; j++) {
        unsigned w = wv[j];
#pragma unroll
        for (int k = 0; k < 4; k++) {
            int v = (int)(signed char)(w >> (8 * k));
            int c = j * 4 + k;
            m |= (unsigned long long)(v > s_ti[c]) << c;
        }
    }
    return m;
}

// ---------------- thresh1 -> xp2 bits + xb2 floats ----------------
__global__ void k_thresh1(const float* __restrict__ gg, const float* __restrict__ bb,
                          float* __restrict__ out) {
    __shared__ int s_ti[48];
    __shared__ unsigned long long s_bits[154];
    int b = blockIdx.x, tid = threadIdx.x;
    if (tid < 48) s_ti[tid] = compute_thresh(0, tid, (double)BATCH * 154.0, 1.0, gg, bb);
    __syncthreads();
    if (tid < 154) {
        unsigned long long m = cmp48(g_pool1t + (size_t)b * 462 + tid * 3, s_ti);
        s_bits[tid] = m;
        g_xp2[b * 154 + tid] = m;
    }
    __syncthreads();
    float4* dst = (float4*)(out + XB2_OFF + (size_t)b * 7392);
    for (int f = tid; f < 1848; f += 256) {
        int e = f * 4;
        int c = e / 154, p = e - c * 154;
        float r[4];
#pragma unroll
        for (int i = 0; i < 4; i++) {
            int pi = p + i, ci = c;
            if (pi >= 154) { pi -= 154; ci += 1; }
            r[i] = ((unsigned)(s_bits[pi] >> ci) & 1u) ? 1.f : -1.f;
        }
        dst[f] = make_float4(r[0], r[1], r[2], r[3]);
    }
}

// ---------------- conv2 (pad0) + stats, half-domain transposed out -----------
__global__ void k_conv2(const float* __restrict__ gg) {
    __shared__ unsigned long long s_in[154];
    __shared__ unsigned long long s_w[432];
    __shared__ uint4 s_t84[108 * 3];                    // 108*48 bytes
    __shared__ int s_sum[48], s_sq[48];
    signed char* s_t8 = (signed char*)s_t84;
    int b = blockIdx.x, tid = threadIdx.x;
    int lane = tid & 31, wid = tid >> 5;
    if (tid < 154) s_in[tid] = g_xp2[b * 154 + tid];
    for (int i = tid; i < 432; i += 256) s_w[i] = g_wp2[i];
    __syncthreads();
    for (int o = wid; o < 48; o += 8) {
        unsigned long long rw[9];
#pragma unroll
        for (int t = 0; t < 9; t++) rw[t] = s_w[o * 9 + t];
        int neg = (gg[o] < 0.f) ? -1 : 1;
        int sum = 0, sq = 0;
        for (int p = lane; p < 108; p += 32) {
            int h = p / 12, w = p % 12;
            const unsigned long long* in = s_in + h * 14 + w;
            int pc = __popcll(in[ 0] ^ rw[0]) + __popcll(in[ 1] ^ rw[1]) + __popcll(in[ 2] ^ rw[2])
                   + __popcll(in[14] ^ rw[3]) + __popcll(in[15] ^ rw[4]) + __popcll(in[16] ^ rw[5])
                   + __popcll(in[28] ^ rw[6]) + __popcll(in[29] ^ rw[7]) + __popcll(in[30] ^ rw[8]);
            int u = 216 - pc;
            s_t8[p * 48 + o] = (signed char)(neg * u);
            sum += u; sq += u * u;
        }
        sum = __reduce_add_sync(0xffffffffu, sum);
        sq  = __reduce_add_sync(0xffffffffu, sq);
        if (lane == 0) { s_sum[o] = sum; s_sq[o] = sq; }
    }
    __syncthreads();
    {
        uint4* dp = g_conv2t + (size_t)b * 324;
        for (int i = tid; i < 324; i += 256) dp[i] = s_t84[i];
    }
    if (tid < 48) {
        atomicAdd((unsigned long long*)&g_S[48 + tid], (unsigned long long)(long long)s_sum[tid]);
        atomicAdd((unsigned long long*)&g_SS[48 + tid], (unsigned long long)(long long)s_sq[tid]);
    }
}

// ---------------- thresh2 -> xp3 bits + xb3 floats ----------------
__global__ void k_thresh2(const float* __restrict__ gg, const float* __restrict__ bb,
                          float* __restrict__ out) {
    __shared__ int s_ti[48];
    __shared__ unsigned long long s_bits[108];
    int b = blockIdx.x, tid = threadIdx.x;
    if (tid < 48) s_ti[tid] = compute_thresh(1, tid, (double)BATCH * 108.0, 2.0, gg, bb);
    __syncthreads();
    if (tid < 108) {
        unsigned long long m = cmp48(g_conv2t + (size_t)b * 324 + tid * 3, s_ti);
        s_bits[tid] = m;
        g_xp3[b * 108 + tid] = m;
    }
    __syncthreads();
    float4* dst = (float4*)(out + XB3_OFF + (size_t)b * 5184);
    for (int f = tid; f < 1296; f += 256) {
        int c = f / 27, p = (f % 27) * 4;
        float4 v;
        v.x = ((unsigned)(s_bits[p + 0] >> c) & 1u) ? 1.f : -1.f;
        v.y = ((unsigned)(s_bits[p + 1] >> c) & 1u) ? 1.f : -1.f;
        v.z = ((unsigned)(s_bits[p + 2] >> c) & 1u) ? 1.f : -1.f;
        v.w = ((unsigned)(s_bits[p + 3] >> c) & 1u) ? 1.f : -1.f;
        dst[f] = v;
    }
}

// ---------------- conv3 (pad0) + maxpool(2,1) + stats, transposed out --------
__global__ void k_conv3(const float* __restrict__ gg) {
    __shared__ unsigned long long s_in[108];
    __shared__ unsigned long long s_w[432];
    __shared__ uint4 s_conv4[70 * 3];                   // 70*48 bytes
    __shared__ uint4 s_pt4[54 * 3];                     // 54*48 bytes
    __shared__ int s_sum[48], s_sq[48];
    signed char* s_conv = (signed char*)s_conv4;
    signed char* s_pt = (signed char*)s_pt4;
    int b = blockIdx.x, tid = threadIdx.x;
    int lane = tid & 31, wid = tid >> 5;
    if (tid < 108) s_in[tid] = g_xp3[b * 108 + tid];
    for (int i = tid; i < 432; i += 256) s_w[i] = g_wp3[i];
    __syncthreads();
    for (int o = wid; o < 48; o += 8) {
        unsigned long long rw[9];
#pragma unroll
        for (int t = 0; t < 9; t++) rw[t] = s_w[o * 9 + t];
        for (int p = lane; p < 70; p += 32) {
            int h = p / 10, w = p % 10;
            const unsigned long long* in = s_in + h * 12 + w;
            int pc = __popcll(in[ 0] ^ rw[0]) + __popcll(in[ 1] ^ rw[1]) + __popcll(in[ 2] ^ rw[2])
                   + __popcll(in[12] ^ rw[3]) + __popcll(in[13] ^ rw[4]) + __popcll(in[14] ^ rw[5])
                   + __popcll(in[24] ^ rw[6]) + __popcll(in[25] ^ rw[7]) + __popcll(in[26] ^ rw[8]);
            s_conv[p * 48 + o] = (signed char)(216 - pc);   // half-domain
        }
    }
    __syncthreads();
    for (int o = wid; o < 48; o += 8) {
        int neg = (gg[o] < 0.f) ? -1 : 1;
        int sum = 0, sq = 0;
        for (int p = lane; p < 54; p += 32) {
            int i = p / 9, j = p % 9;
            const signed char* base = s_conv + (i * 10 + j) * 48 + o;
            int m = max(max((int)base[0], (int)base[48]), max((int)base[480], (int)base[528]));
            s_pt[p * 48 + o] = (signed char)(neg * m);
            sum += m; sq += m * m;
        }
        sum = __reduce_add_sync(0xffffffffu, sum);
        sq  = __reduce_add_sync(0xffffffffu, sq);
        if (lane == 0) { s_sum[o] = sum; s_sq[o] = sq; }
    }
    __syncthreads();
    {
        uint4* dp = g_pool3t + (size_t)b * 162;
        for (int i = tid; i < 162; i += 256) dp[i] = s_pt4[i];
    }
    if (tid < 48) {
        atomicAdd((unsigned long long*)&g_S[96 + tid], (unsigned long long)(long long)s_sum[tid]);
        atomicAdd((unsigned long long*)&g_SS[96 + tid], (unsigned long long)(long long)s_sq[tid]);
    }
}

// ---------------- final: threshold -> fb bits+floats; FC via popcount --------
__global__ void k_final(const float* __restrict__ gg, const float* __restrict__ bb,
                        float* __restrict__ out) {
    __shared__ unsigned long long s_bits[54];
    __shared__ unsigned s_fb[81];
    __shared__ unsigned s_wfc[405];
    __shared__ int s_ti[48];
    int b = blockIdx.x, tid = threadIdx.x;
    int lane = tid & 31, wid = tid >> 5;
    if (tid < 48) s_ti[tid] = compute_thresh(2, tid, (double)BATCH * 54.0, 2.0, gg, bb);
    for (int i = tid; i < 405; i += 256) s_wfc[i] = g_wfcp[i];
    __syncthreads();
    if (tid < 54)
        s_bits[tid] = cmp48(g_pool3t + (size_t)b * 162 + tid * 3, s_ti);
    __syncthreads();
    for (int i = wid; i < 81; i += 8) {
        int k = i * 32 + lane;          // 81*32 == 2592; k = o*54+p
        int o = k / 54, p = k - o * 54;
        bool bit = (unsigned)(s_bits[p] >> o) & 1u;
        unsigned wmask = __ballot_sync(0xffffffffu, bit);
        if (lane == 0) s_fb[i] = wmask;
    }
    __syncthreads();
    // fb floats
    float4* dst = (float4*)(out + FB_OFF + (size_t)b * 2592);
    for (int f = tid; f < 648; f += 256) {
        int e = f * 4;
        unsigned w = s_fb[e >> 5] >> (e & 31);
        float4 v;
        v.x = (w & 1u) ? 1.f : -1.f;
        v.y = ((w >> 1) & 1u) ? 1.f : -1.f;
        v.z = ((w >> 2) & 1u) ? 1.f : -1.f;
        v.w = ((w >> 3) & 1u) ? 1.f : -1.f;
        dst[f] = v;
    }
    if (wid < 5) {
        int mm = 0;
        for (int l = lane; l < 81; l += 32)
            mm += __popc(s_fb[l] ^ s_wfc[wid * 81 + l]);
        mm = __reduce_add_sync(0xffffffffu, mm);
        if (lane == 0) out[(size_t)b * 5 + wid] = (float)(2592 - 2 * mm);
    }
}

// ---------------- launcher ----------------
extern "C" void kernel_launch(void* const* d_in, const int* in_sizes, int n_in,
                              void* d_out, int out_size) {
    const float* x   = (const float*)d_in[0];
    const float* g1  = (const float*)d_in[2];
    const float* b1  = (const float*)d_in[3];
    const float* g2  = (const float*)d_in[5];
    const float* b2  = (const float*)d_in[6];
    const float* g3  = (const float*)d_in[8];
    const float* b3  = (const float*)d_in[9];
    float* out = (float*)d_out;

    k_pack_w<<<1, 512>>>((const float*)d_in[1], (const float*)d_in[4],
                         (const float*)d_in[7], (const float*)d_in[10]);
    k_pack_x<<<(BATCH * 45 + 255) / 256, 256>>>(x, out);
    k_conv1<<<BATCH, 256>>>(g1);
    k_thresh1<<<BATCH, 256>>>(g1, b1, out);
    k_conv2<<<BATCH, 256>>>(g2);
    k_thresh2<<<BATCH, 256>>>(g2, b2, out);
    k_conv3<<<BATCH, 256>>>(g3);
    k_final<<<BATCH, 256>>>(g3, b3, out);
}

// round 15
// speedup vs baseline: 2.0440x; 1.0578x over previous
#include <cuda_runtime.h>
#include <math.h>

// Binarized AlexNet_OWT, XNOR-popcount formulation.
// R14: 5 launches. Threshold+expand fused into consumer convs; pack_x fused
// into conv1. Intermediates: transposed [b][pos][ch] int8, sign-folded.

#define BATCH 4096

#define XB1_OFF 20480u
#define XB2_OFF 8867840u
#define XB3_OFF 39145472u
#define FB_OFF  60379136u

// ---------------- scratch (static __device__; no allocations) ----------------
__device__ unsigned short      g_wp1[48 * 9];
__device__ unsigned long long  g_wp2[48 * 9];
__device__ unsigned long long  g_wp3[48 * 9];
__device__ unsigned int        g_wfcp[5 * 81];
__device__ uint4               g_pool1t[BATCH * 462];  // [b][154][48] s8, sign-folded (g1)
__device__ uint4               g_conv2t[BATCH * 324];  // [b][108][48] s8 half-domain, sign-folded (g2)
__device__ uint4               g_pool3t[BATCH * 162];  // [b][54][48] s8 half-domain, sign-folded (g3)
__device__ long long           g_S[3 * 48];
__device__ long long           g_SS[3 * 48];

// ---------------- weight packing + stat zeroing ----------------
__global__ void k_pack_w(const float* __restrict__ w1, const float* __restrict__ w2,
                         const float* __restrict__ w3, const float* __restrict__ wfc) {
    int tid = threadIdx.x;
    for (int idx = tid; idx < 432; idx += blockDim.x) {
        int o = idx / 9, t = idx % 9;
        unsigned m1 = 0;
        for (int c = 0; c < 12; c++) m1 |= (unsigned)(w1[o * 108 + c * 9 + t] > 0.f) << c;
        g_wp1[idx] = (unsigned short)m1;
        unsigned long long m2 = 0ull, m3 = 0ull;
        for (int c = 0; c < 48; c++) {
            m2 |= (unsigned long long)(w2[o * 432 + c * 9 + t] > 0.f) << c;
            m3 |= (unsigned long long)(w3[o * 432 + c * 9 + t] > 0.f) << c;
        }
        g_wp2[idx] = m2;
        g_wp3[idx] = m3;
    }
    for (int idx = tid; idx < 405; idx += blockDim.x) {
        int o = idx / 81, wi = idx % 81;
        unsigned m = 0;
        for (int l = 0; l < 32; l++)
            m |= (unsigned)(wfc[o * 2592 + wi * 32 + l] > 0.f) << l;
        g_wfcp[idx] = m;
    }
    for (int idx = tid; idx < 144; idx += blockDim.x) { g_S[idx] = 0; g_SS[idx] = 0; }
}

// helper: sign-folded integer threshold for channel c.
// Producers store v' = sgn(g_c)*v; bit = (v' > ti) with ti = floor(sgn*thr).
__device__ __forceinline__ int compute_thresh(int level, int c, double N, double scale,
                                              const float* gg, const float* bb) {
    double S = scale * (double)g_S[level * 48 + c];
    double SS = scale * scale * (double)g_SS[level * 48 + c];
    double mean = S / N;
    double var = SS / N - mean * mean;
    double sd = sqrt(var + 1e-5);
    double g = (double)gg[c], b = (double)bb[c];
    double thr_u = (mean - b * sd / g) / scale;
    return (int)floor(g >= 0.0 ? thr_u : -thr_u);
}

// ---------------- compare 48 sign-folded bytes -> 48-bit mask ----------------
__device__ __forceinline__ unsigned long long cmp48(const uint4* src, const int* s_ti) {
    uint4 wa = src[0], wb = src[1], wc = src[2];
    unsigned wv[12] = {wa.x, wa.y, wa.z, wa.w, wb.x, wb.y, wb.z, wb.w,
                       wc.x, wc.y, wc.z, wc.w};
    unsigned long long m = 0ull;
#pragma unroll
    for (int j = 0; j < 12; j++) {
        unsigned w = wv[j];
#pragma unroll
        for (int k = 0; k < 4; k++) {
            int v = (int)(signed char)(w >> (8 * k));
            int c = j * 4 + k;
            m |= (unsigned long long)(v > s_ti[c]) << c;
        }
    }
    return m;
}

// ---------------- conv1: x -> xb1 floats + bits; conv(pad1)+pool+stats -------
__global__ void k_conv1(const float* __restrict__ x, const float* __restrict__ gg,
                        float* __restrict__ out) {
    __shared__ unsigned short s_in[180];
    __shared__ unsigned short s_w[432];
    __shared__ uint4 s_conv4[540];                      // 48*180 bytes
    __shared__ uint4 s_pt4[154 * 3];                    // 154*48 bytes
    __shared__ int s_sum[48], s_sq[48];
    signed char* s_conv = (signed char*)s_conv4;
    signed char* s_pt = (signed char*)s_pt4;
    int b = blockIdx.x, tid = threadIdx.x;
    int lane = tid & 31, wid = tid >> 5;
    for (int i = tid; i < 432; i += 256) s_w[i] = g_wp1[i];
    // binarize+pack input: thread q handles 4 consecutive spatial positions
    if (tid < 45) {
        const float4* xb = (const float4*)(x + (size_t)b * 2160) + tid;
        float4* ob = (float4*)(out + XB1_OFF + (size_t)b * 2160) + tid;
        unsigned short m[4] = {0, 0, 0, 0};
#pragma unroll
        for (int c = 0; c < 12; c++) {
            float4 v = xb[c * 45];
            bool b0 = v.x > 0.f, b1 = v.y > 0.f, b2 = v.z > 0.f, b3 = v.w > 0.f;
            m[0] |= (unsigned short)(b0 << c);
            m[1] |= (unsigned short)(b1 << c);
            m[2] |= (unsigned short)(b2 << c);
            m[3] |= (unsigned short)(b3 << c);
            ob[c * 45] = make_float4(b0 ? 1.f : -1.f, b1 ? 1.f : -1.f,
                                     b2 ? 1.f : -1.f, b3 ? 1.f : -1.f);
        }
        s_in[4 * tid + 0] = m[0];
        s_in[4 * tid + 1] = m[1];
        s_in[4 * tid + 2] = m[2];
        s_in[4 * tid + 3] = m[3];
    }
    __syncthreads();

    for (int o = wid; o < 48; o += 8) {
        unsigned rw[9];
#pragma unroll
        for (int t = 0; t < 9; t++) rw[t] = s_w[o * 9 + t];
        for (int p = lane; p < 180; p += 32) {
            int h = p / 15, w = p % 15;
            int acc;
            if ((unsigned)(h - 1) <= 9u && (unsigned)(w - 1) <= 12u) {
                int base = (h - 1) * 15 + (w - 1);
                int pc = __popc((unsigned)(s_in[base +  0] ^ rw[0]))
                       + __popc((unsigned)(s_in[base +  1] ^ rw[1]))
                       + __popc((unsigned)(s_in[base +  2] ^ rw[2]))
                       + __popc((unsigned)(s_in[base + 15] ^ rw[3]))
                       + __popc((unsigned)(s_in[base + 16] ^ rw[4]))
                       + __popc((unsigned)(s_in[base + 17] ^ rw[5]))
                       + __popc((unsigned)(s_in[base + 30] ^ rw[6]))
                       + __popc((unsigned)(s_in[base + 31] ^ rw[7]))
                       + __popc((unsigned)(s_in[base + 32] ^ rw[8]));
                acc = 108 - 2 * pc;
            } else {
                acc = 0;
#pragma unroll
                for (int kh = 0; kh < 3; kh++) {
                    int ih = h + kh - 1;
                    if ((unsigned)ih >= 12u) continue;
#pragma unroll
                    for (int kw = 0; kw < 3; kw++) {
                        int iw = w + kw - 1;
                        if ((unsigned)iw >= 15u) continue;
                        acc += 12 - 2 * __popc((unsigned)(s_in[ih * 15 + iw] ^ rw[kh * 3 + kw]));
                    }
                }
            }
            s_conv[o * 180 + p] = (signed char)acc;
        }
    }
    __syncthreads();

    for (int o = wid; o < 48; o += 8) {
        int neg = (gg[o] < 0.f) ? -1 : 1;
        int sum = 0, sq = 0;
        for (int p = lane; p < 154; p += 32) {
            int i = p / 14, j = p % 14;
            const signed char* base = s_conv + o * 180 + i * 15 + j;
            int m = max(max((int)base[0], (int)base[1]), max((int)base[15], (int)base[16]));
            s_pt[p * 48 + o] = (signed char)(neg * m);
            sum += m; sq += m * m;
        }
        sum = __reduce_add_sync(0xffffffffu, sum);
        sq  = __reduce_add_sync(0xffffffffu, sq);
        if (lane == 0) { s_sum[o] = sum; s_sq[o] = sq; }
    }
    __syncthreads();
    {
        uint4* dp = g_pool1t + (size_t)b * 462;
        for (int i = tid; i < 462; i += 256) dp[i] = s_pt4[i];
    }
    if (tid < 48) {
        atomicAdd((unsigned long long*)&g_S[tid], (unsigned long long)(long long)s_sum[tid]);
        atomicAdd((unsigned long long*)&g_SS[tid], (unsigned long long)(long long)s_sq[tid]);
    }
}

// ---------------- conv2: thresh(L0) -> xb2 floats + bits; conv(pad0)+stats ---
__global__ void k_conv2(const float* __restrict__ g1, const float* __restrict__ b1,
                        const float* __restrict__ g2, float* __restrict__ out) {
    __shared__ unsigned long long s_in[154];
    __shared__ unsigned long long s_w[432];
    __shared__ uint4 s_t84[108 * 3];                    // 108*48 bytes
    __shared__ int s_ti[48];
    __shared__ int s_sum[48], s_sq[48];
    signed char* s_t8 = (signed char*)s_t84;
    int b = blockIdx.x, tid = threadIdx.x;
    int lane = tid & 31, wid = tid >> 5;
    for (int i = tid; i < 432; i += 256) s_w[i] = g_wp2[i];
    if (tid < 48) s_ti[tid] = compute_thresh(0, tid, (double)BATCH * 154.0, 1.0, g1, b1);
    __syncthreads();
    if (tid < 154)
        s_in[tid] = cmp48(g_pool1t + (size_t)b * 462 + tid * 3, s_ti);
    __syncthreads();
    // expand xb2 floats from bits
    {
        float4* dst = (float4*)(out + XB2_OFF + (size_t)b * 7392);
        for (int f = tid; f < 1848; f += 256) {
            int e = f * 4;
            int c = e / 154, p = e - c * 154;
            float r[4];
#pragma unroll
            for (int i = 0; i < 4; i++) {
                int pi = p + i, ci = c;
                if (pi >= 154) { pi -= 154; ci += 1; }
                r[i] = ((unsigned)(s_in[pi] >> ci) & 1u) ? 1.f : -1.f;
            }
            dst[f] = make_float4(r[0], r[1], r[2], r[3]);
        }
    }
    for (int o = wid; o < 48; o += 8) {
        unsigned long long rw[9];
#pragma unroll
        for (int t = 0; t < 9; t++) rw[t] = s_w[o * 9 + t];
        int neg = (g2[o] < 0.f) ? -1 : 1;
        int sum = 0, sq = 0;
        for (int p = lane; p < 108; p += 32) {
            int h = p / 12, w = p % 12;
            const unsigned long long* in = s_in + h * 14 + w;
            int pc = __popcll(in[ 0] ^ rw[0]) + __popcll(in[ 1] ^ rw[1]) + __popcll(in[ 2] ^ rw[2])
                   + __popcll(in[14] ^ rw[3]) + __popcll(in[15] ^ rw[4]) + __popcll(in[16] ^ rw[5])
                   + __popcll(in[28] ^ rw[6]) + __popcll(in[29] ^ rw[7]) + __popcll(in[30] ^ rw[8]);
            int u = 216 - pc;
            s_t8[p * 48 + o] = (signed char)(neg * u);
            sum += u; sq += u * u;
        }
        sum = __reduce_add_sync(0xffffffffu, sum);
        sq  = __reduce_add_sync(0xffffffffu, sq);
        if (lane == 0) { s_sum[o] = sum; s_sq[o] = sq; }
    }
    __syncthreads();
    {
        uint4* dp = g_conv2t + (size_t)b * 324;
        for (int i = tid; i < 324; i += 256) dp[i] = s_t84[i];
    }
    if (tid < 48) {
        atomicAdd((unsigned long long*)&g_S[48 + tid], (unsigned long long)(long long)s_sum[tid]);
        atomicAdd((unsigned long long*)&g_SS[48 + tid], (unsigned long long)(long long)s_sq[tid]);
    }
}

// ---------------- conv3: thresh(L1) -> xb3 floats + bits; conv+pool+stats ----
__global__ void k_conv3(const float* __restrict__ g2, const float* __restrict__ b2,
                        const float* __restrict__ g3, float* __restrict__ out) {
    __shared__ unsigned long long s_in[108];
    __shared__ unsigned long long s_w[432];
    __shared__ uint4 s_conv4[70 * 3];                   // 70*48 bytes
    __shared__ uint4 s_pt4[54 * 3];                     // 54*48 bytes
    __shared__ int s_ti[48];
    __shared__ int s_sum[48], s_sq[48];
    signed char* s_conv = (signed char*)s_conv4;
    signed char* s_pt = (signed char*)s_pt4;
    int b = blockIdx.x, tid = threadIdx.x;
    int lane = tid & 31, wid = tid >> 5;
    for (int i = tid; i < 432; i += 256) s_w[i] = g_wp3[i];
    if (tid < 48) s_ti[tid] = compute_thresh(1, tid, (double)BATCH * 108.0, 2.0, g2, b2);
    __syncthreads();
    if (tid < 108)
        s_in[tid] = cmp48(g_conv2t + (size_t)b * 324 + tid * 3, s_ti);
    __syncthreads();
    // expand xb3 floats from bits
    {
        float4* dst = (float4*)(out + XB3_OFF + (size_t)b * 5184);
        for (int f = tid; f < 1296; f += 256) {
            int c = f / 27, p = (f % 27) * 4;
            float4 v;
            v.x = ((unsigned)(s_in[p + 0] >> c) & 1u) ? 1.f : -1.f;
            v.y = ((unsigned)(s_in[p + 1] >> c) & 1u) ? 1.f : -1.f;
            v.z = ((unsigned)(s_in[p + 2] >> c) & 1u) ? 1.f : -1.f;
            v.w = ((unsigned)(s_in[p + 3] >> c) & 1u) ? 1.f : -1.f;
            dst[f] = v;
        }
    }
    for (int o = wid; o < 48; o += 8) {
        unsigned long long rw[9];
#pragma unroll
        for (int t = 0; t < 9; t++) rw[t] = s_w[o * 9 + t];
        for (int p = lane; p < 70; p += 32) {
            int h = p / 10, w = p % 10;
            const unsigned long long* in = s_in + h * 12 + w;
            int pc = __popcll(in[ 0] ^ rw[0]) + __popcll(in[ 1] ^ rw[1]) + __popcll(in[ 2] ^ rw[2])
                   + __popcll(in[12] ^ rw[3]) + __popcll(in[13] ^ rw[4]) + __popcll(in[14] ^ rw[5])
                   + __popcll(in[24] ^ rw[6]) + __popcll(in[25] ^ rw[7]) + __popcll(in[26] ^ rw[8]);
            s_conv[p * 48 + o] = (signed char)(216 - pc);   // half-domain
        }
    }
    __syncthreads();
    for (int o = wid; o < 48; o += 8) {
        int neg = (g3[o] < 0.f) ? -1 : 1;
        int sum = 0, sq = 0;
        for (int p = lane; p < 54; p += 32) {
            int i = p / 9, j = p % 9;
            const signed char* base = s_conv + (i * 10 + j) * 48 + o;
            int m = max(max((int)base[0], (int)base[48]), max((int)base[480], (int)base[528]));
            s_pt[p * 48 + o] = (signed char)(neg * m);
            sum += m; sq += m * m;
        }
        sum = __reduce_add_sync(0xffffffffu, sum);
        sq  = __reduce_add_sync(0xffffffffu, sq);
        if (lane == 0) { s_sum[o] = sum; s_sq[o] = sq; }
    }
    __syncthreads();
    {
        uint4* dp = g_pool3t + (size_t)b * 162;
        for (int i = tid; i < 162; i += 256) dp[i] = s_pt4[i];
    }
    if (tid < 48) {
        atomicAdd((unsigned long long*)&g_S[96 + tid], (unsigned long long)(long long)s_sum[tid]);
        atomicAdd((unsigned long long*)&g_SS[96 + tid], (unsigned long long)(long long)s_sq[tid]);
    }
}

// ---------------- final: thresh(L2) -> fb bits+floats; FC via popcount -------
__global__ void k_final(const float* __restrict__ gg, const float* __restrict__ bb,
                        float* __restrict__ out) {
    __shared__ unsigned long long s_bits[54];
    __shared__ unsigned s_fb[81];
    __shared__ unsigned s_wfc[405];
    __shared__ int s_ti[48];
    int b = blockIdx.x, tid = threadIdx.x;
    int lane = tid & 31, wid = tid >> 5;
    if (tid < 48) s_ti[tid] = compute_thresh(2, tid, (double)BATCH * 54.0, 2.0, gg, bb);
    for (int i = tid; i < 405; i += 256) s_wfc[i] = g_wfcp[i];
    __syncthreads();
    if (tid < 54)
        s_bits[tid] = cmp48(g_pool3t + (size_t)b * 162 + tid * 3, s_ti);
    __syncthreads();
    for (int i = wid; i < 81; i += 8) {
        int k = i * 32 + lane;          // 81*32 == 2592; k = o*54+p
        int o = k / 54, p = k - o * 54;
        bool bit = (unsigned)(s_bits[p] >> o) & 1u;
        unsigned wmask = __ballot_sync(0xffffffffu, bit);
        if (lane == 0) s_fb[i] = wmask;
    }
    __syncthreads();
    float4* dst = (float4*)(out + FB_OFF + (size_t)b * 2592);
    for (int f = tid; f < 648; f += 256) {
        int e = f * 4;
        unsigned w = s_fb[e >> 5] >> (e & 31);
        float4 v;
        v.x = (w & 1u) ? 1.f : -1.f;
        v.y = ((w >> 1) & 1u) ? 1.f : -1.f;
        v.z = ((w >> 2) & 1u) ? 1.f : -1.f;
        v.w = ((w >> 3) & 1u) ? 1.f : -1.f;
        dst[f] = v;
    }
    if (wid < 5) {
        int mm = 0;
        for (int l = lane; l < 81; l += 32)
            mm += __popc(s_fb[l] ^ s_wfc[wid * 81 + l]);
        mm = __reduce_add_sync(0xffffffffu, mm);
        if (lane == 0) out[(size_t)b * 5 + wid] = (float)(2592 - 2 * mm);
    }
}

// ---------------- launcher ----------------
extern "C" void kernel_launch(void* const* d_in, const int* in_sizes, int n_in,
                              void* d_out, int out_size) {
    const float* x   = (const float*)d_in[0];
    const float* g1  = (const float*)d_in[2];
    const float* b1  = (const float*)d_in[3];
    const float* g2  = (const float*)d_in[5];
    const float* b2  = (const float*)d_in[6];
    const float* g3  = (const float*)d_in[8];
    const float* b3  = (const float*)d_in[9];
    float* out = (float*)d_out;

    k_pack_w<<<1, 512>>>((const float*)d_in[1], (const float*)d_in[4],
                         (const float*)d_in[7], (const float*)d_in[10]);
    k_conv1<<<BATCH, 256>>>(x, g1, out);
    k_conv2<<<BATCH, 256>>>(g1, b1, g2, out);
    k_conv3<<<BATCH, 256>>>(g2, b2, g3, out);
    k_final<<<BATCH, 256>>>(g3, b3, out);
}

// round 16
// speedup vs baseline: 2.4581x; 1.2026x over previous
#include <cuda_runtime.h>
#include <math.h>

// Binarized AlexNet_OWT, XNOR-popcount formulation.
// R16: LSU-cut round. Row-sweep sliding-window conv2/conv3 with channel
// pairing (each loaded input word feeds 2 channels), channel-paired conv1,
// 52-byte padded transposed smem rows (conflict-free byte stores), compact
// 48-byte global rows via u32 remap copy. 5 launches.

#define BATCH 4096

#define XB1_OFF 20480u
#define XB2_OFF 8867840u
#define XB3_OFF 39145472u
#define FB_OFF  60379136u

typedef unsigned long long u64;

// ---------------- scratch (static __device__; no allocations) ----------------
__device__ unsigned short      g_wp1[48 * 9];
__device__ u64                 g_wp2[48 * 9];
__device__ u64                 g_wp3[48 * 9];
__device__ unsigned int        g_wfcp[5 * 81];
__device__ uint4               g_pool1t[BATCH * 462];  // [b][154][48] s8, sign-folded (g1)
__device__ uint4               g_conv2t[BATCH * 324];  // [b][108][48] s8 half-domain, sign-folded (g2)
__device__ uint4               g_pool3t[BATCH * 162];  // [b][54][48] s8 half-domain, sign-folded (g3)
__device__ long long           g_S[3 * 48];
__device__ long long           g_SS[3 * 48];

// ---------------- weight packing + stat zeroing ----------------
__global__ void k_pack_w(const float* __restrict__ w1, const float* __restrict__ w2,
                         const float* __restrict__ w3, const float* __restrict__ wfc) {
    int tid = threadIdx.x;
    for (int idx = tid; idx < 432; idx += blockDim.x) {
        int o = idx / 9, t = idx % 9;
        unsigned m1 = 0;
        for (int c = 0; c < 12; c++) m1 |= (unsigned)(w1[o * 108 + c * 9 + t] > 0.f) << c;
        g_wp1[idx] = (unsigned short)m1;
        u64 m2 = 0ull, m3 = 0ull;
        for (int c = 0; c < 48; c++) {
            m2 |= (u64)(w2[o * 432 + c * 9 + t] > 0.f) << c;
            m3 |= (u64)(w3[o * 432 + c * 9 + t] > 0.f) << c;
        }
        g_wp2[idx] = m2;
        g_wp3[idx] = m3;
    }
    for (int idx = tid; idx < 405; idx += blockDim.x) {
        int o = idx / 81, wi = idx % 81;
        unsigned m = 0;
        for (int l = 0; l < 32; l++)
            m |= (unsigned)(wfc[o * 2592 + wi * 32 + l] > 0.f) << l;
        g_wfcp[idx] = m;
    }
    for (int idx = tid; idx < 144; idx += blockDim.x) { g_S[idx] = 0; g_SS[idx] = 0; }
}

// helper: sign-folded integer threshold for channel c.
__device__ __forceinline__ int compute_thresh(int level, int c, double N, double scale,
                                              const float* gg, const float* bb) {
    double S = scale * (double)g_S[level * 48 + c];
    double SS = scale * scale * (double)g_SS[level * 48 + c];
    double mean = S / N;
    double var = SS / N - mean * mean;
    double sd = sqrt(var + 1e-5);
    double g = (double)gg[c], b = (double)bb[c];
    double thr_u = (mean - b * sd / g) / scale;
    return (int)floor(g >= 0.0 ? thr_u : -thr_u);
}

// ---------------- compare 48 sign-folded bytes -> 48-bit mask ----------------
__device__ __forceinline__ u64 cmp48(const uint4* src, const int* s_ti) {
    uint4 wa = src[0], wb = src[1], wc = src[2];
    unsigned wv[12] = {wa.x, wa.y, wa.z, wa.w, wb.x, wb.y, wb.z, wb.w,
                       wc.x, wc.y, wc.z, wc.w};
    u64 m = 0ull;
#pragma unroll
    for (int j = 0; j < 12; j++) {
        unsigned w = wv[j];
#pragma unroll
        for (int k = 0; k < 4; k++) {
            int v = (int)(signed char)(w >> (8 * k));
            int c = j * 4 + k;
            m |= (u64)(v > s_ti[c]) << c;
        }
    }
    return m;
}

// ---------------- conv1: x -> xb1 floats + bits; conv(pad1)+pool+stats -------
__global__ void __launch_bounds__(256) k_conv1(const float* __restrict__ x,
                                               const float* __restrict__ gg,
                                               float* __restrict__ out) {
    __shared__ unsigned short s_in[180];
    __shared__ unsigned short s_w[432];
    __shared__ uint4 s_conv4[540];                      // [o][p] 48*180 bytes
    __shared__ uint4 s_pt4[501];                        // [p][o] 154 rows x 52B
    __shared__ int s_sum[48], s_sq[48];
    signed char* s_conv = (signed char*)s_conv4;
    signed char* s_pt = (signed char*)s_pt4;
    int b = blockIdx.x, tid = threadIdx.x;
    int lane = tid & 31, wid = tid >> 5;
    for (int i = tid; i < 432; i += 256) s_w[i] = g_wp1[i];
    if (tid < 45) {
        const float4* xb = (const float4*)(x + (size_t)b * 2160) + tid;
        float4* ob = (float4*)(out + XB1_OFF + (size_t)b * 2160) + tid;
        unsigned short m[4] = {0, 0, 0, 0};
#pragma unroll
        for (int c = 0; c < 12; c++) {
            float4 v = xb[c * 45];
            bool b0 = v.x > 0.f, b1 = v.y > 0.f, b2 = v.z > 0.f, b3 = v.w > 0.f;
            m[0] |= (unsigned short)(b0 << c);
            m[1] |= (unsigned short)(b1 << c);
            m[2] |= (unsigned short)(b2 << c);
            m[3] |= (unsigned short)(b3 << c);
            ob[c * 45] = make_float4(b0 ? 1.f : -1.f, b1 ? 1.f : -1.f,
                                     b2 ? 1.f : -1.f, b3 ? 1.f : -1.f);
        }
        s_in[4 * tid + 0] = m[0];
        s_in[4 * tid + 1] = m[1];
        s_in[4 * tid + 2] = m[2];
        s_in[4 * tid + 3] = m[3];
    }
    __syncthreads();

    // conv mainloop: channel pairs (oA, oA+24) share input loads
#pragma unroll
    for (int pr = 0; pr < 3; pr++) {
        int oA = wid + 8 * pr, oB = oA + 24;
        unsigned rwA[9], rwB[9];
#pragma unroll
        for (int t = 0; t < 9; t++) { rwA[t] = s_w[oA * 9 + t]; rwB[t] = s_w[oB * 9 + t]; }
        for (int p = lane; p < 180; p += 32) {
            int h = p / 15, w = p % 15;
            int accA, accB;
            if ((unsigned)(h - 1) <= 9u && (unsigned)(w - 1) <= 12u) {
                int base = (h - 1) * 15 + (w - 1);
                unsigned v0 = s_in[base +  0], v1 = s_in[base +  1], v2 = s_in[base +  2];
                unsigned v3 = s_in[base + 15], v4 = s_in[base + 16], v5 = s_in[base + 17];
                unsigned v6 = s_in[base + 30], v7 = s_in[base + 31], v8 = s_in[base + 32];
                int pcA = __popc(v0 ^ rwA[0]) + __popc(v1 ^ rwA[1]) + __popc(v2 ^ rwA[2])
                        + __popc(v3 ^ rwA[3]) + __popc(v4 ^ rwA[4]) + __popc(v5 ^ rwA[5])
                        + __popc(v6 ^ rwA[6]) + __popc(v7 ^ rwA[7]) + __popc(v8 ^ rwA[8]);
                int pcB = __popc(v0 ^ rwB[0]) + __popc(v1 ^ rwB[1]) + __popc(v2 ^ rwB[2])
                        + __popc(v3 ^ rwB[3]) + __popc(v4 ^ rwB[4]) + __popc(v5 ^ rwB[5])
                        + __popc(v6 ^ rwB[6]) + __popc(v7 ^ rwB[7]) + __popc(v8 ^ rwB[8]);
                accA = 108 - 2 * pcA;
                accB = 108 - 2 * pcB;
            } else {
                accA = 0; accB = 0;
#pragma unroll
                for (int kh = 0; kh < 3; kh++) {
                    int ih = h + kh - 1;
                    if ((unsigned)ih >= 12u) continue;
#pragma unroll
                    for (int kw = 0; kw < 3; kw++) {
                        int iw = w + kw - 1;
                        if ((unsigned)iw >= 15u) continue;
                        unsigned v = s_in[ih * 15 + iw];
                        accA += 12 - 2 * __popc(v ^ rwA[kh * 3 + kw]);
                        accB += 12 - 2 * __popc(v ^ rwB[kh * 3 + kw]);
                    }
                }
            }
            s_conv[oA * 180 + p] = (signed char)accA;
            s_conv[oB * 180 + p] = (signed char)accB;
        }
    }
    __syncthreads();

    for (int o = wid; o < 48; o += 8) {
        int neg = (gg[o] < 0.f) ? -1 : 1;
        int sum = 0, sq = 0;
        for (int p = lane; p < 154; p += 32) {
            int i = p / 14, j = p % 14;
            const signed char* base = s_conv + o * 180 + i * 15 + j;
            int m = max(max((int)base[0], (int)base[1]), max((int)base[15], (int)base[16]));
            s_pt[p * 52 + o] = (signed char)(neg * m);
            sum += m; sq += m * m;
        }
        sum = __reduce_add_sync(0xffffffffu, sum);
        sq  = __reduce_add_sync(0xffffffffu, sq);
        if (lane == 0) { s_sum[o] = sum; s_sq[o] = sq; }
    }
    __syncthreads();
    {
        // remap compact copy: 154 rows, 12 u32/row from 13-u32 padded rows
        const unsigned* sp = (const unsigned*)s_pt4;
        unsigned* dp = (unsigned*)(g_pool1t + (size_t)b * 462);
        for (int i = tid; i < 1848; i += 256) {
            int r = i / 12, w = i % 12;
            dp[i] = sp[r * 13 + w];
        }
    }
    if (tid < 48) {
        atomicAdd((u64*)&g_S[tid], (u64)(long long)s_sum[tid]);
        atomicAdd((u64*)&g_SS[tid], (u64)(long long)s_sq[tid]);
    }
}

// ---------------- conv2: thresh(L0) -> xb2 floats + bits; sweep conv+stats ---
__global__ void __launch_bounds__(256) k_conv2(const float* __restrict__ g1,
                                               const float* __restrict__ b1,
                                               const float* __restrict__ g2,
                                               float* __restrict__ out) {
    __shared__ u64 s_in[154];
    __shared__ u64 s_w[432];
    __shared__ uint4 s_t84[351];                        // [p][o] 108 rows x 52B
    __shared__ int s_ti[48];
    __shared__ int s_sum[48], s_sq[48];
    signed char* s_t8 = (signed char*)s_t84;
    int b = blockIdx.x, tid = threadIdx.x;
    int lane = tid & 31, wid = tid >> 5;
    for (int i = tid; i < 432; i += 256) s_w[i] = g_wp2[i];
    if (tid < 48) {
        s_ti[tid] = compute_thresh(0, tid, (double)BATCH * 154.0, 1.0, g1, b1);
        s_sum[tid] = 0; s_sq[tid] = 0;
    }
    __syncthreads();
    if (tid < 154)
        s_in[tid] = cmp48(g_pool1t + (size_t)b * 462 + tid * 3, s_ti);
    __syncthreads();
    // expand xb2 floats from bits
    {
        float4* dst = (float4*)(out + XB2_OFF + (size_t)b * 7392);
        for (int f = tid; f < 1848; f += 256) {
            int e = f * 4;
            int c = e / 154, p = e - c * 154;
            float r[4];
#pragma unroll
            for (int i = 0; i < 4; i++) {
                int pi = p + i, ci = c;
                if (pi >= 154) { pi -= 154; ci += 1; }
                r[i] = ((unsigned)(s_in[pi] >> ci) & 1u) ? 1.f : -1.f;
            }
            dst[f] = make_float4(r[0], r[1], r[2], r[3]);
        }
    }
    // sweep conv: lane = pair*9 + h (27 active lanes / warp)
    if (lane < 27) {
        int pr = lane / 9, h = lane % 9;
        int oA = wid + 8 * pr, oB = oA + 24;
        u64 rwA[9], rwB[9];
#pragma unroll
        for (int t = 0; t < 9; t++) { rwA[t] = s_w[oA * 9 + t]; rwB[t] = s_w[oB * 9 + t]; }
        int negA = (g2[oA] < 0.f) ? -1 : 1;
        int negB = (g2[oB] < 0.f) ? -1 : 1;
        const u64* row = s_in + h * 14;
        u64 p0 = 0, p1 = 0, p2 = 0, q0 = 0, q1 = 0, q2 = 0;
        int sumA = 0, sqA = 0, sumB = 0, sqB = 0;
#pragma unroll
        for (int c = 0; c < 14; c++) {
            u64 x0 = row[c], x1 = row[c + 14], x2 = row[c + 28];
            if (c >= 2) {
                int pcA = __popcll(p0 ^ rwA[0]) + __popcll(q0 ^ rwA[1]) + __popcll(x0 ^ rwA[2])
                        + __popcll(p1 ^ rwA[3]) + __popcll(q1 ^ rwA[4]) + __popcll(x1 ^ rwA[5])
                        + __popcll(p2 ^ rwA[6]) + __popcll(q2 ^ rwA[7]) + __popcll(x2 ^ rwA[8]);
                int pcB = __popcll(p0 ^ rwB[0]) + __popcll(q0 ^ rwB[1]) + __popcll(x0 ^ rwB[2])
                        + __popcll(p1 ^ rwB[3]) + __popcll(q1 ^ rwB[4]) + __popcll(x1 ^ rwB[5])
                        + __popcll(p2 ^ rwB[6]) + __popcll(q2 ^ rwB[7]) + __popcll(x2 ^ rwB[8]);
                int uA = 216 - pcA, uB = 216 - pcB;
                int prow = (h * 12 + c - 2) * 52;
                s_t8[prow + oA] = (signed char)(negA * uA);
                s_t8[prow + oB] = (signed char)(negB * uB);
                sumA += uA; sqA += uA * uA;
                sumB += uB; sqB += uB * uB;
            }
            p0 = q0; p1 = q1; p2 = q2;
            q0 = x0; q1 = x1; q2 = x2;
        }
        atomicAdd(&s_sum[oA], sumA); atomicAdd(&s_sq[oA], sqA);
        atomicAdd(&s_sum[oB], sumB); atomicAdd(&s_sq[oB], sqB);
    }
    __syncthreads();
    {
        const unsigned* sp = (const unsigned*)s_t84;
        unsigned* dp = (unsigned*)(g_conv2t + (size_t)b * 324);
        for (int i = tid; i < 1296; i += 256) {
            int r = i / 12, w = i % 12;
            dp[i] = sp[r * 13 + w];
        }
    }
    if (tid < 48) {
        atomicAdd((u64*)&g_S[48 + tid], (u64)(long long)s_sum[tid]);
        atomicAdd((u64*)&g_SS[48 + tid], (u64)(long long)s_sq[tid]);
    }
}

// ---------------- conv3: thresh(L1) -> xb3 floats + bits; sweep conv+pool ----
__global__ void __launch_bounds__(256) k_conv3(const float* __restrict__ g2,
                                               const float* __restrict__ b2,
                                               const float* __restrict__ g3,
                                               float* __restrict__ out) {
    __shared__ u64 s_in[108];
    __shared__ u64 s_w[432];
    __shared__ uint4 s_conv4[228];                      // [p][o] 70 rows x 52B
    __shared__ uint4 s_pt4[176];                        // [p][o] 54 rows x 52B
    __shared__ int s_ti[48];
    __shared__ int s_sum[48], s_sq[48];
    signed char* s_conv = (signed char*)s_conv4;
    signed char* s_pt = (signed char*)s_pt4;
    int b = blockIdx.x, tid = threadIdx.x;
    int lane = tid & 31, wid = tid >> 5;
    for (int i = tid; i < 432; i += 256) s_w[i] = g_wp3[i];
    if (tid < 48) s_ti[tid] = compute_thresh(1, tid, (double)BATCH * 108.0, 2.0, g2, b2);
    __syncthreads();
    if (tid < 108)
        s_in[tid] = cmp48(g_conv2t + (size_t)b * 324 + tid * 3, s_ti);
    __syncthreads();
    // expand xb3 floats from bits
    {
        float4* dst = (float4*)(out + XB3_OFF + (size_t)b * 5184);
        for (int f = tid; f < 1296; f += 256) {
            int c = f / 27, p = (f % 27) * 4;
            float4 v;
            v.x = ((unsigned)(s_in[p + 0] >> c) & 1u) ? 1.f : -1.f;
            v.y = ((unsigned)(s_in[p + 1] >> c) & 1u) ? 1.f : -1.f;
            v.z = ((unsigned)(s_in[p + 2] >> c) & 1u) ? 1.f : -1.f;
            v.w = ((unsigned)(s_in[p + 3] >> c) & 1u) ? 1.f : -1.f;
            dst[f] = v;
        }
    }
    // sweep conv: lane = pair*7 + h (21 active lanes / warp)
    if (lane < 21) {
        int pr = lane / 7, h = lane % 7;
        int oA = wid + 8 * pr, oB = oA + 24;
        u64 rwA[9], rwB[9];
#pragma unroll
        for (int t = 0; t < 9; t++) { rwA[t] = s_w[oA * 9 + t]; rwB[t] = s_w[oB * 9 + t]; }
        const u64* row = s_in + h * 12;
        u64 p0 = 0, p1 = 0, p2 = 0, q0 = 0, q1 = 0, q2 = 0;
#pragma unroll
        for (int c = 0; c < 12; c++) {
            u64 x0 = row[c], x1 = row[c + 12], x2 = row[c + 24];
            if (c >= 2) {
                int pcA = __popcll(p0 ^ rwA[0]) + __popcll(q0 ^ rwA[1]) + __popcll(x0 ^ rwA[2])
                        + __popcll(p1 ^ rwA[3]) + __popcll(q1 ^ rwA[4]) + __popcll(x1 ^ rwA[5])
                        + __popcll(p2 ^ rwA[6]) + __popcll(q2 ^ rwA[7]) + __popcll(x2 ^ rwA[8]);
                int pcB = __popcll(p0 ^ rwB[0]) + __popcll(q0 ^ rwB[1]) + __popcll(x0 ^ rwB[2])
                        + __popcll(p1 ^ rwB[3]) + __popcll(q1 ^ rwB[4]) + __popcll(x1 ^ rwB[5])
                        + __popcll(p2 ^ rwB[6]) + __popcll(q2 ^ rwB[7]) + __popcll(x2 ^ rwB[8]);
                int prow = (h * 10 + c - 2) * 52;
                s_conv[prow + oA] = (signed char)(216 - pcA);   // half-domain
                s_conv[prow + oB] = (signed char)(216 - pcB);
            }
            p0 = q0; p1 = q1; p2 = q2;
            q0 = x0; q1 = x1; q2 = x2;
        }
    }
    __syncthreads();
    for (int o = wid; o < 48; o += 8) {
        int neg = (g3[o] < 0.f) ? -1 : 1;
        int sum = 0, sq = 0;
        for (int p = lane; p < 54; p += 32) {
            int i = p / 9, j = p % 9;
            const signed char* base = s_conv + (i * 10 + j) * 52 + o;
            int m = max(max((int)base[0], (int)base[52]), max((int)base[520], (int)base[572]));
            s_pt[p * 52 + o] = (signed char)(neg * m);
            sum += m; sq += m * m;
        }
        sum = __reduce_add_sync(0xffffffffu, sum);
        sq  = __reduce_add_sync(0xffffffffu, sq);
        if (lane == 0) { s_sum[o] = sum; s_sq[o] = sq; }
    }
    __syncthreads();
    {
        const unsigned* sp = (const unsigned*)s_pt4;
        unsigned* dp = (unsigned*)(g_pool3t + (size_t)b * 162);
        for (int i = tid; i < 648; i += 256) {
            int r = i / 12, w = i % 12;
            dp[i] = sp[r * 13 + w];
        }
    }
    if (tid < 48) {
        atomicAdd((u64*)&g_S[96 + tid], (u64)(long long)s_sum[tid]);
        atomicAdd((u64*)&g_SS[96 + tid], (u64)(long long)s_sq[tid]);
    }
}

// ---------------- final: thresh(L2) -> fb bits+floats; FC via popcount -------
__global__ void k_final(const float* __restrict__ gg, const float* __restrict__ bb,
                        float* __restrict__ out) {
    __shared__ u64 s_bits[54];
    __shared__ unsigned s_fb[81];
    __shared__ unsigned s_wfc[405];
    __shared__ int s_ti[48];
    int b = blockIdx.x, tid = threadIdx.x;
    int lane = tid & 31, wid = tid >> 5;
    if (tid < 48) s_ti[tid] = compute_thresh(2, tid, (double)BATCH * 54.0, 2.0, gg, bb);
    for (int i = tid; i < 405; i += 256) s_wfc[i] = g_wfcp[i];
    __syncthreads();
    if (tid < 54)
        s_bits[tid] = cmp48(g_pool3t + (size_t)b * 162 + tid * 3, s_ti);
    __syncthreads();
    for (int i = wid; i < 81; i += 8) {
        int k = i * 32 + lane;          // 81*32 == 2592; k = o*54+p
        int o = k / 54, p = k - o * 54;
        bool bit = (unsigned)(s_bits[p] >> o) & 1u;
        unsigned wmask = __ballot_sync(0xffffffffu, bit);
        if (lane == 0) s_fb[i] = wmask;
    }
    __syncthreads();
    float4* dst = (float4*)(out + FB_OFF + (size_t)b * 2592);
    for (int f = tid; f < 648; f += 256) {
        int e = f * 4;
        unsigned w = s_fb[e >> 5] >> (e & 31);
        float4 v;
        v.x = (w & 1u) ? 1.f : -1.f;
        v.y = ((w >> 1) & 1u) ? 1.f : -1.f;
        v.z = ((w >> 2) & 1u) ? 1.f : -1.f;
        v.w = ((w >> 3) & 1u) ? 1.f : -1.f;
        dst[f] = v;
    }
    if (wid < 5) {
        int mm = 0;
        for (int l = lane; l < 81; l += 32)
            mm += __popc(s_fb[l] ^ s_wfc[wid * 81 + l]);
        mm = __reduce_add_sync(0xffffffffu, mm);
        if (lane == 0) out[(size_t)b * 5 + wid] = (float)(2592 - 2 * mm);
    }
}

// ---------------- launcher ----------------
extern "C" void kernel_launch(void* const* d_in, const int* in_sizes, int n_in,
                              void* d_out, int out_size) {
    const float* x   = (const float*)d_in[0];
    const float* g1  = (const float*)d_in[2];
    const float* b1  = (const float*)d_in[3];
    const float* g2  = (const float*)d_in[5];
    const float* b2  = (const float*)d_in[6];
    const float* g3  = (const float*)d_in[8];
    const float* b3  = (const float*)d_in[9];
    float* out = (float*)d_out;

    k_pack_w<<<1, 512>>>((const float*)d_in[1], (const float*)d_in[4],
                         (const float*)d_in[7], (const float*)d_in[10]);
    k_conv1<<<BATCH, 256>>>(x, g1, out);
    k_conv2<<<BATCH, 256>>>(g1, b1, g2, out);
    k_conv3<<<BATCH, 256>>>(g2, b2, g3, out);
    k_final<<<BATCH, 256>>>(g3, b3, out);
}